// round 7
// baseline (speedup 1.0000x reference)
#include <cuda_runtime.h>
#include <cuda_bf16.h>
#include <math.h>
#include <stdint.h>

#define BB 32
#define TT 512
#define EE 512
#define HH 512
#define CC 32
#define MM (BB*TT)        /* 16384 token positions, m' = t*32 + b */
#define G4 (4*HH)         /* 2048 gate columns per direction */
#define NBLK 128          /* persistent LSTM grid: 64 blocks per direction */

/* ------------------------ scratch (static device memory) ------------------- */
__device__ __nv_bfloat16 g_embh[(size_t)MM*EE];    /* layer0 GEMM input (bf16) */
__device__ __nv_bfloat16 g_l0h[(size_t)MM*2*HH];   /* layer0 output     (bf16) */
__device__ __nv_bfloat16 g_Wbf[2*(size_t)G4*EE + 2*(size_t)G4*2*HH]; /* Wih bf16 */
__device__ __nv_bfloat16 g_Whbf[4*(size_t)G4*HH];  /* Whh bf16 (4 matrices)    */
__device__ float g_xw0[(size_t)MM*G4];             /* xw forward  [m'][2048]   */
__device__ float g_xw1[(size_t)MM*G4];             /* xw backward [m'][2048]   */
__device__ float g_l1out[(size_t)MM*2*HH];         /* layer1 output [m'][1024] */
__device__ __nv_bfloat16 g_hbuf_bf[2*2*BB*HH];     /* [dir][parity][b][h] bf16 */
__device__ unsigned g_bar_cnt[2] = {0, 0};
__device__ unsigned g_bar_gen[2] = {0, 0};

/* Wbf offsets (Wih) */
#define WOFF_L0F ((size_t)0)
#define WOFF_L0B ((size_t)G4*EE)
#define WOFF_L1F ((size_t)2*G4*EE)
#define WOFF_L1B ((size_t)2*G4*EE + (size_t)G4*2*HH)
/* Whbf offsets (Whh) */
#define WH_L0F ((size_t)0)
#define WH_L0B ((size_t)G4*HH)
#define WH_L1F ((size_t)2*G4*HH)
#define WH_L1B ((size_t)3*G4*HH)

/* --------------------- per-direction grid barrier (64 blocks) -------------- */
__device__ __forceinline__ void dir_sync(int dir) {
    __syncthreads();
    if (threadIdx.x == 0) {
        unsigned gen = *(volatile unsigned*)&g_bar_gen[dir];
        __threadfence();
        if (atomicAdd(&g_bar_cnt[dir], 1u) == (NBLK/2) - 1) {
            atomicExch(&g_bar_cnt[dir], 0u);
            __threadfence();
            atomicAdd(&g_bar_gen[dir], 1u);
        } else {
            while (*(volatile unsigned*)&g_bar_gen[dir] == gen) { }
        }
        __threadfence();
    }
    __syncthreads();
}

/* ------------------------------ embedding (f32 -> bf16) -------------------- */
__global__ __launch_bounds__(256) void embed_kernel(const int* __restrict__ x,
                                                    const float* __restrict__ emb) {
    int gid  = blockIdx.x * blockDim.x + threadIdx.x;
    int mp   = gid >> 5;
    int lane = gid & 31;
    int b  = mp & 31;
    int tt = mp >> 5;
    int v  = x[b*TT + tt];
    const float4* src = (const float4*)(emb + (size_t)v*EE);
    __nv_bfloat162* dst = (__nv_bfloat162*)(g_embh + (size_t)mp*EE);
#pragma unroll
    for (int r = 0; r < EE/128; r++) {
        float4 f = src[r*32 + lane];
        dst[(r*32 + lane)*2 + 0] = __floats2bfloat162_rn(f.x, f.y);
        dst[(r*32 + lane)*2 + 1] = __floats2bfloat162_rn(f.z, f.w);
    }
}

/* --------------------------- f32 -> bf16 convert --------------------------- */
__global__ __launch_bounds__(256) void f2bf_kernel(const float* __restrict__ src,
                                                   __nv_bfloat16* __restrict__ dst,
                                                   int n4) {
    int i = blockIdx.x * blockDim.x + threadIdx.x;
    if (i < n4) {
        float4 f = *(const float4*)(src + (size_t)i*4);
        __nv_bfloat162* d = (__nv_bfloat162*)(dst + (size_t)i*4);
        d[0] = __floats2bfloat162_rn(f.x, f.y);
        d[1] = __floats2bfloat162_rn(f.z, f.w);
    }
}

/* ----------------------------- mma helpers --------------------------------- */
__device__ __forceinline__ void ldmatrix_x4(uint32_t& d0, uint32_t& d1,
                                            uint32_t& d2, uint32_t& d3,
                                            uint32_t addr) {
    asm volatile("ldmatrix.sync.aligned.m8n8.x4.shared.b16 {%0,%1,%2,%3}, [%4];"
                 : "=r"(d0), "=r"(d1), "=r"(d2), "=r"(d3) : "r"(addr));
}
__device__ __forceinline__ void mma_bf16(float* c, const uint32_t* a, const uint32_t* b) {
    asm volatile("mma.sync.aligned.m16n8k16.row.col.f32.bf16.bf16.f32 "
                 "{%0,%1,%2,%3}, {%4,%5,%6,%7}, {%8,%9}, {%0,%1,%2,%3};"
                 : "+f"(c[0]), "+f"(c[1]), "+f"(c[2]), "+f"(c[3])
                 : "r"(a[0]), "r"(a[1]), "r"(a[2]), "r"(a[3]), "r"(b[0]), "r"(b[1]));
}

/* ---------------- bf16 tensor-core GEMM: xw = A @ W^T + bih + bhh ---------- */
#define GBM 128
#define GBN 128
#define GBK 32
#define LDS_W 40

__global__ __launch_bounds__(256) void gemm_bf16_kernel(
        int layer,
        const float* __restrict__ bif, const float* __restrict__ bhf,
        const float* __restrict__ bib, const float* __restrict__ bhb) {
    const int K = layer ? 2*HH : EE;
    const __nv_bfloat16* A = layer ? g_l0h : g_embh;
    int dir = blockIdx.z;
    const __nv_bfloat16* W = g_Wbf + (layer ? (dir ? WOFF_L1B : WOFF_L1F)
                                            : (dir ? WOFF_L0B : WOFF_L0F));
    const float* bi = dir ? bib : bif;
    const float* bh = dir ? bhb : bhf;
    float* out = dir ? g_xw1 : g_xw0;

    __shared__ __nv_bfloat16 As[GBM*LDS_W];
    __shared__ __nv_bfloat16 Bs[GBN*LDS_W];

    int t = threadIdx.x;
    int m0 = blockIdx.y * GBM;
    int n0 = blockIdx.x * GBN;
    int warp = t >> 5, lane = t & 31;
    int wm0 = (warp & 3) * 32;
    int wn0 = (warp >> 2) * 64;

    int lr = t >> 2;
    int lc = (t & 3) * 8;
    const __nv_bfloat16* Ag = A + (size_t)(m0 + lr) * K + lc;
    const __nv_bfloat16* Wg = W + (size_t)(n0 + lr) * K + lc;

    float c[2][8][4];
#pragma unroll
    for (int i = 0; i < 2; i++)
#pragma unroll
        for (int j = 0; j < 8; j++)
#pragma unroll
            for (int q = 0; q < 4; q++) c[i][j][q] = 0.f;

    int arow = (lane & 7) + ((lane >> 3) & 1) * 8;
    int acol = (lane >> 4) * 8;
    int brow = ((lane >> 4) * 8) + (lane & 7);
    int bcol = ((lane >> 3) & 1) * 8;

    uint32_t as_base = (uint32_t)__cvta_generic_to_shared(As);
    uint32_t bs_base = (uint32_t)__cvta_generic_to_shared(Bs);

    const int nk = K / GBK;
    uint4 pa0 = *(const uint4*)(Ag);
    uint4 pa1 = *(const uint4*)(Ag + (size_t)64*K);
    uint4 pb0 = *(const uint4*)(Wg);
    uint4 pb1 = *(const uint4*)(Wg + (size_t)64*K);

    for (int kt = 0; kt < nk; kt++) {
        *(uint4*)(As + lr*LDS_W + lc)        = pa0;
        *(uint4*)(As + (lr+64)*LDS_W + lc)   = pa1;
        *(uint4*)(Bs + lr*LDS_W + lc)        = pb0;
        *(uint4*)(Bs + (lr+64)*LDS_W + lc)   = pb1;
        __syncthreads();
        if (kt + 1 < nk) {
            int ko = (kt + 1) * GBK;
            pa0 = *(const uint4*)(Ag + ko);
            pa1 = *(const uint4*)(Ag + (size_t)64*K + ko);
            pb0 = *(const uint4*)(Wg + ko);
            pb1 = *(const uint4*)(Wg + (size_t)64*K + ko);
        }
#pragma unroll
        for (int ks = 0; ks < GBK; ks += 16) {
            uint32_t a[2][4];
            uint32_t b[8][2];
#pragma unroll
            for (int mt = 0; mt < 2; mt++) {
                uint32_t addr = as_base +
                    (uint32_t)(((wm0 + mt*16 + arow)*LDS_W + ks + acol) * 2);
                ldmatrix_x4(a[mt][0], a[mt][1], a[mt][2], a[mt][3], addr);
            }
#pragma unroll
            for (int p = 0; p < 4; p++) {
                uint32_t addr = bs_base +
                    (uint32_t)(((wn0 + p*16 + brow)*LDS_W + ks + bcol) * 2);
                ldmatrix_x4(b[2*p][0], b[2*p][1], b[2*p+1][0], b[2*p+1][1], addr);
            }
#pragma unroll
            for (int mt = 0; mt < 2; mt++)
#pragma unroll
                for (int nt = 0; nt < 8; nt++)
                    mma_bf16(c[mt][nt], a[mt], b[nt]);
        }
        __syncthreads();
    }

    int g  = lane >> 2;
    int cp = (lane & 3) * 2;
#pragma unroll
    for (int nt = 0; nt < 8; nt++) {
        int n = n0 + wn0 + nt*8 + cp;
        float b0 = bi[n]   + bh[n];
        float b1 = bi[n+1] + bh[n+1];
#pragma unroll
        for (int mt = 0; mt < 2; mt++) {
            int r = m0 + wm0 + mt*16 + g;
            float2 v0 = make_float2(c[mt][nt][0] + b0, c[mt][nt][1] + b1);
            float2 v1 = make_float2(c[mt][nt][2] + b0, c[mt][nt][3] + b1);
            *(float2*)(out + (size_t)r*G4 + n)       = v0;
            *(float2*)(out + (size_t)(r+8)*G4 + n)   = v1;
        }
    }
}

/* ------------------- persistent recurrent scan (bf16 MMA) ------------------ */
#define LW 520                       /* bf16 row stride: 1040B, %128 = 16 -> LDSM conflict-free */
#define GST 34                       /* gate smem row stride (floats) */
#define LSTM_SMEM (32*LW*2*2 + 2*32*GST*4)

__global__ __launch_bounds__(256) void lstm_mma_kernel(int layer) {
    extern __shared__ __align__(16) char smraw[];
    __nv_bfloat16* h_s = (__nv_bfloat16*)smraw;   /* [32][LW] h_{t-1}  */
    __nv_bfloat16* W_s = h_s + 32*LW;             /* [32][LW] Whh slice */
    float* G_s = (float*)(W_s + 32*LW);           /* [2][32][GST] gate partials */

    int t = threadIdx.x;
    int warp = t >> 5, lane = t & 31;
    int dir = blockIdx.x >> 6;
    int hb  = (blockIdx.x & 63) << 3;
    const __nv_bfloat16* Whh = g_Whbf + (layer ? (dir ? WH_L1B : WH_L1F)
                                               : (dir ? WH_L0B : WH_L0F));
    const float* xw = dir ? g_xw1 : g_xw0;
    __nv_bfloat16* hbuf = g_hbuf_bf + dir*2*BB*HH;

    /* stage Whh slice once: W_s[g*8+j][k] <- Whh[g*512 + hb + j][k] */
    {
        int r  = t >> 3;              /* 0..31 */
        int g  = r >> 3, j = r & 7;
        int kq = (t & 7) * 64;
        const uint4* src = (const uint4*)(Whh + (size_t)(g*HH + hb + j)*HH + kq);
        uint4* dst = (uint4*)(W_s + r*LW + kq);
#pragma unroll
        for (int i = 0; i < 8; i++) dst[i] = src[i];
    }

    /* warp tile: 2(M16) x 2(N16) x 2(K256) */
    int mb = (warp & 1) * 16;
    int nb = ((warp >> 1) & 1) * 16;
    int kb = (warp >> 2) * 256;
    float* Gk = G_s + (warp >> 2) * 32 * GST;

    int arow = (lane & 7) + ((lane >> 3) & 1) * 8;
    int acol = (lane >> 4) * 8;
    int brow = ((lane >> 4) * 8) + (lane & 7);
    int bcol = ((lane >> 3) & 1) * 8;
    uint32_t hs_base = (uint32_t)__cvta_generic_to_shared(h_s);
    uint32_t ws_base = (uint32_t)__cvta_generic_to_shared(W_s);

    /* gate-math mapping: thread -> (batch gb, local hcol gj) */
    int gb = t >> 3;
    int gj = t & 7;

    float c = 0.f;

    for (int it = 0; it < TT; it++) {
        int tstep = dir ? (TT - 1 - it) : it;

        /* prefetch xw for this thread's gate math (independent of h) */
        const float* xp = xw + (size_t)(tstep*32 + gb)*G4 + hb + gj;
        float x0 = __ldg(xp + 0*HH);
        float x1 = __ldg(xp + 1*HH);
        float x2 = __ldg(xp + 2*HH);
        float x3 = __ldg(xp + 3*HH);

        /* stage h_{t-1} (32x512 bf16 = 32KB) */
        {
            int r  = t >> 3;
            int kq = (t & 7) * 64;
            uint4* dst = (uint4*)(h_s + r*LW + kq);
            if (it == 0) {
                uint4 z = make_uint4(0u,0u,0u,0u);
#pragma unroll
                for (int i = 0; i < 8; i++) dst[i] = z;
            } else {
                const uint4* src = (const uint4*)(hbuf + ((it & 1) ? BB*HH : 0) + r*HH + kq);
#pragma unroll
                for (int i = 0; i < 8; i++) dst[i] = __ldcg(src + i);
            }
        }
        __syncthreads();

        float acc[2][4];
#pragma unroll
        for (int nt = 0; nt < 2; nt++)
#pragma unroll
            for (int q = 0; q < 4; q++) acc[nt][q] = 0.f;

#pragma unroll
        for (int ks = 0; ks < 16; ks++) {
            uint32_t a[4], b0[2], b1[2];
            uint32_t addrA = hs_base + (uint32_t)(((mb + arow)*LW + kb + ks*16 + acol) * 2);
            ldmatrix_x4(a[0], a[1], a[2], a[3], addrA);
            uint32_t addrB = ws_base + (uint32_t)(((nb + brow)*LW + kb + ks*16 + bcol) * 2);
            ldmatrix_x4(b0[0], b0[1], b1[0], b1[1], addrB);
            mma_bf16(acc[0], a, b0);
            mma_bf16(acc[1], a, b1);
        }

        /* C fragments -> gate smem (K-split partials) */
        {
            int g  = lane >> 2;
            int cp = (lane & 3) * 2;
#pragma unroll
            for (int nt = 0; nt < 2; nt++) {
                *(float2*)(Gk + (mb + g)*GST     + nb + nt*8 + cp) = make_float2(acc[nt][0], acc[nt][1]);
                *(float2*)(Gk + (mb + g + 8)*GST + nb + nt*8 + cp) = make_float2(acc[nt][2], acc[nt][3]);
            }
        }
        __syncthreads();

        /* gate math: thread (gb, gj); gate rows g*8+gj in the 32-row slice */
        {
            float a0 = x0 + G_s[gb*GST + 0*8 + gj] + G_s[32*GST + gb*GST + 0*8 + gj];
            float a1 = x1 + G_s[gb*GST + 1*8 + gj] + G_s[32*GST + gb*GST + 1*8 + gj];
            float a2 = x2 + G_s[gb*GST + 2*8 + gj] + G_s[32*GST + gb*GST + 2*8 + gj];
            float a3 = x3 + G_s[gb*GST + 3*8 + gj] + G_s[32*GST + gb*GST + 3*8 + gj];
            float ig = 1.f / (1.f + expf(-a0));
            float fg = 1.f / (1.f + expf(-a1));
            float gg = tanhf(a2);
            float og = 1.f / (1.f + expf(-a3));
            c = fg*c + ig*gg;
            float hv = og * tanhf(c);
            __nv_bfloat16 hbv = __float2bfloat16(hv);
            hbuf[(((it + 1) & 1) ? BB*HH : 0) + gb*HH + hb + gj] = hbv;
            if (layer == 0)
                g_l0h[(size_t)(tstep*32 + gb)*(2*HH) + dir*HH + hb + gj] = hbv;
            else
                g_l1out[(size_t)(tstep*32 + gb)*(2*HH) + dir*HH + hb + gj] = hv;
        }
        __threadfence();
        dir_sync(dir);
    }
}

/* --------------------- classifier + log_softmax + transpose ---------------- */
__global__ __launch_bounds__(256) void cls_kernel(const float* __restrict__ truth,
        const int* __restrict__ tf, const float* __restrict__ Wc,
        const float* __restrict__ bc, float* __restrict__ out) {
    __shared__ float Fs[64*68];
    __shared__ float Ws[32*68];
    __shared__ float Ls[64*33];
    __shared__ float lse[64];

    int t  = threadIdx.x;
    int p0 = blockIdx.x * 64;
    int p  = t & 63, cg = t >> 6;

    float acc[8];
#pragma unroll
    for (int j = 0; j < 8; j++) acc[j] = 0.f;

    for (int kc = 0; kc < 2*HH; kc += 64) {
        __syncthreads();
#pragma unroll
        for (int pass = 0; pass < 4; pass++) {
            int pp = pass*16 + (t >> 4);
            int kq = (t & 15) * 4;
            *(float4*)(Fs + pp*68 + kq) =
                *(const float4*)(g_l1out + (size_t)(p0 + pp)*(2*HH) + kc + kq);
        }
        {
            int cc = t >> 3, j0 = (t & 7) * 8;
            const float* src = Wc + (size_t)cc*(2*HH + 1) + 1 + kc + j0;
            float* dst = Ws + cc*68 + j0;
#pragma unroll
            for (int i = 0; i < 8; i++) dst[i] = src[i];
        }
        __syncthreads();
#pragma unroll
        for (int kk = 0; kk < 16; kk++) {
            float4 f = *(const float4*)(Fs + p*68 + kk*4);
#pragma unroll
            for (int j = 0; j < 8; j++) {
                float4 wv = *(const float4*)(Ws + (cg*8 + j)*68 + kk*4);
                acc[j] = fmaf(f.x,wv.x, fmaf(f.y,wv.y, fmaf(f.z,wv.z, fmaf(f.w,wv.w, acc[j]))));
            }
        }
    }

    int mp = p0 + p;
    int b  = mp & 31;
    int tt = mp >> 5;
    float past = 0.f;
    if (tt > 0 && tf[0] != 0) past = truth[b*TT + tt - 1];
#pragma unroll
    for (int j = 0; j < 8; j++) {
        int cc = cg*8 + j;
        acc[j] += bc[cc] + past * Wc[(size_t)cc*(2*HH + 1)];
        Ls[p*33 + cc] = acc[j];
    }
    __syncthreads();
    if (t < 64) {
        float m = -1e30f;
#pragma unroll
        for (int cc = 0; cc < CC; cc++) m = fmaxf(m, Ls[t*33 + cc]);
        float s = 0.f;
#pragma unroll
        for (int cc = 0; cc < CC; cc++) s += expf(Ls[t*33 + cc] - m);
        lse[t] = m + logf(s);
    }
    __syncthreads();
    {
        float l = lse[p];
#pragma unroll
        for (int j = 0; j < 8; j++) {
            int cc = cg*8 + j;
            out[(size_t)b*CC*TT + (size_t)cc*TT + tt] = Ls[p*33 + cc] - l;
        }
    }
}

/* ------------------------------- launch ------------------------------------ */
extern "C" void kernel_launch(void* const* d_in, const int* in_sizes, int n_in,
                              void* d_out, int out_size) {
    (void)in_sizes; (void)n_in; (void)out_size;
    const int*   x     = (const int*)  d_in[0];
    const float* truth = (const float*)d_in[1];
    const int*   tf    = (const int*)  d_in[2];
    const float* emb   = (const float*)d_in[3];
    const float* Wih0f = (const float*)d_in[4];
    const float* Whh0f = (const float*)d_in[5];
    const float* bih0f = (const float*)d_in[6];
    const float* bhh0f = (const float*)d_in[7];
    const float* Wih0b = (const float*)d_in[8];
    const float* Whh0b = (const float*)d_in[9];
    const float* bih0b = (const float*)d_in[10];
    const float* bhh0b = (const float*)d_in[11];
    const float* Wih1f = (const float*)d_in[12];
    const float* Whh1f = (const float*)d_in[13];
    const float* bih1f = (const float*)d_in[14];
    const float* bhh1f = (const float*)d_in[15];
    const float* Wih1b = (const float*)d_in[16];
    const float* Whh1b = (const float*)d_in[17];
    const float* bih1b = (const float*)d_in[18];
    const float* bhh1b = (const float*)d_in[19];
    const float* Wc    = (const float*)d_in[20];
    const float* bc    = (const float*)d_in[21];
    float* out = (float*)d_out;

    cudaFuncSetAttribute(lstm_mma_kernel,
                         cudaFuncAttributeMaxDynamicSharedMemorySize, LSTM_SMEM);

    __nv_bfloat16* wbf = nullptr;
    cudaGetSymbolAddress((void**)&wbf, g_Wbf);
    __nv_bfloat16* whbf = nullptr;
    cudaGetSymbolAddress((void**)&whbf, g_Whbf);

    embed_kernel<<<MM/8, 256>>>(x, emb);

    /* convert Wih + Whh matrices to bf16 */
    {
        int n0 = G4*EE  / 4;   /* 2048*512/4  */
        int n1 = G4*2*HH / 4;  /* 2048*1024/4 */
        int nh = G4*HH  / 4;   /* 2048*512/4  */
        f2bf_kernel<<<(n0+255)/256, 256>>>(Wih0f, wbf + WOFF_L0F, n0);
        f2bf_kernel<<<(n0+255)/256, 256>>>(Wih0b, wbf + WOFF_L0B, n0);
        f2bf_kernel<<<(n1+255)/256, 256>>>(Wih1f, wbf + WOFF_L1F, n1);
        f2bf_kernel<<<(n1+255)/256, 256>>>(Wih1b, wbf + WOFF_L1B, n1);
        f2bf_kernel<<<(nh+255)/256, 256>>>(Whh0f, whbf + WH_L0F, nh);
        f2bf_kernel<<<(nh+255)/256, 256>>>(Whh0b, whbf + WH_L0B, nh);
        f2bf_kernel<<<(nh+255)/256, 256>>>(Whh1f, whbf + WH_L1F, nh);
        f2bf_kernel<<<(nh+255)/256, 256>>>(Whh1b, whbf + WH_L1B, nh);
    }

    dim3 g0(G4/GBN, MM/GBM, 2);   /* 16 x 128 x 2 */
    gemm_bf16_kernel<<<g0, 256>>>(0, bih0f, bhh0f, bih0b, bhh0b);
    lstm_mma_kernel<<<NBLK, 256, LSTM_SMEM>>>(0);

    gemm_bf16_kernel<<<g0, 256>>>(1, bih1f, bhh1f, bih1b, bhh1b);
    lstm_mma_kernel<<<NBLK, 256, LSTM_SMEM>>>(1);

    cls_kernel<<<MM/64, 256>>>(truth, tf, Wc, bc, out);
}

// round 9
// speedup vs baseline: 1.1577x; 1.1577x over previous
#include <cuda_runtime.h>
#include <cuda_bf16.h>
#include <math.h>
#include <stdint.h>

#define BB 32
#define TT 512
#define EE 512
#define HH 512
#define CC 32
#define MM (BB*TT)        /* 16384 token positions, m' = t*32 + b */
#define G4 (4*HH)         /* 2048 gate columns per direction */
#define NBLK 128          /* persistent LSTM grid: 64 blocks per direction */
#define NB2  (NBLK/2)

/* ------------------------ scratch (static device memory) ------------------- */
__device__ __nv_bfloat16 g_embh[(size_t)MM*EE];    /* layer0 GEMM input (bf16) */
__device__ __nv_bfloat16 g_l0h[(size_t)MM*2*HH];   /* layer0 output     (bf16) */
__device__ __nv_bfloat16 g_Wbf[2*(size_t)G4*EE + 2*(size_t)G4*2*HH]; /* Wih bf16 */
__device__ __nv_bfloat16 g_Whbf[4*(size_t)G4*HH];  /* Whh bf16 (4 matrices)    */
__device__ float g_xw0[(size_t)MM*G4];             /* xw forward  [m'][2048]   */
__device__ float g_xw1[(size_t)MM*G4];             /* xw backward [m'][2048]   */
__device__ float g_l1out[(size_t)MM*2*HH];         /* layer1 output [m'][1024] */
__device__ __nv_bfloat16 g_hbuf_bf[2*2*BB*HH];     /* [dir][parity][b][h] bf16 */
__device__ unsigned g_bar_cnt[2] = {0, 0};
__device__ unsigned g_bar_gen[2] = {0, 0};

/* Wbf offsets (Wih) */
#define WOFF_L0F ((size_t)0)
#define WOFF_L0B ((size_t)G4*EE)
#define WOFF_L1F ((size_t)2*G4*EE)
#define WOFF_L1B ((size_t)2*G4*EE + (size_t)G4*2*HH)
/* Whbf offsets (Whh) */
#define WH_L0F ((size_t)0)
#define WH_L0B ((size_t)G4*HH)
#define WH_L1F ((size_t)2*G4*HH)
#define WH_L1B ((size_t)3*G4*HH)

/* ------------------ acq/rel atomic helpers (gpu scope) --------------------- */
__device__ __forceinline__ unsigned ld_acq(const unsigned* p) {
    unsigned v;
    asm volatile("ld.acquire.gpu.global.u32 %0, [%1];" : "=r"(v) : "l"(p) : "memory");
    return v;
}
__device__ __forceinline__ unsigned atom_add_acqrel(unsigned* p, unsigned v) {
    unsigned old;
    asm volatile("atom.acq_rel.gpu.global.add.u32 %0, [%1], %2;"
                 : "=r"(old) : "l"(p), "r"(v) : "memory");
    return old;
}
__device__ __forceinline__ void red_add_rel(unsigned* p, unsigned v) {
    asm volatile("red.release.gpu.global.add.u32 [%0], %1;" :: "l"(p), "r"(v) : "memory");
}
__device__ __forceinline__ void st_rlx(unsigned* p, unsigned v) {
    asm volatile("st.relaxed.gpu.global.u32 [%0], %1;" :: "l"(p), "r"(v) : "memory");
}

/* --------------------- per-direction grid barrier (64 blocks) --------------
 * release/acquire pattern; no per-thread fences needed: __syncthreads gives
 * intra-block happens-before into thread 0's release-arrive (cumulative).   */
__device__ __forceinline__ void dir_sync(int dir) {
    __syncthreads();
    if (threadIdx.x == 0) {
        unsigned gen = ld_acq(&g_bar_gen[dir]);     /* stable until all arrive */
        unsigned prev = atom_add_acqrel(&g_bar_cnt[dir], 1u);
        if (prev == NB2 - 1) {
            st_rlx(&g_bar_cnt[dir], 0u);
            red_add_rel(&g_bar_gen[dir], 1u);
        }
        while (ld_acq(&g_bar_gen[dir]) == gen) { }
    }
    __syncthreads();
}

/* --------------------------- fast activations ------------------------------ */
__device__ __forceinline__ float tanh_fast(float x) {
    float y;
    asm("tanh.approx.f32 %0, %1;" : "=f"(y) : "f"(x));
    return y;
}
__device__ __forceinline__ float sigmoid_fast(float x) {
    return fmaf(tanh_fast(0.5f * x), 0.5f, 0.5f);
}

/* ------------------------------ embedding (f32 -> bf16) -------------------- */
__global__ __launch_bounds__(256) void embed_kernel(const int* __restrict__ x,
                                                    const float* __restrict__ emb) {
    int gid  = blockIdx.x * blockDim.x + threadIdx.x;
    int mp   = gid >> 5;
    int lane = gid & 31;
    int b  = mp & 31;
    int tt = mp >> 5;
    int v  = x[b*TT + tt];
    const float4* src = (const float4*)(emb + (size_t)v*EE);
    __nv_bfloat162* dst = (__nv_bfloat162*)(g_embh + (size_t)mp*EE);
#pragma unroll
    for (int r = 0; r < EE/128; r++) {
        float4 f = src[r*32 + lane];
        dst[(r*32 + lane)*2 + 0] = __floats2bfloat162_rn(f.x, f.y);
        dst[(r*32 + lane)*2 + 1] = __floats2bfloat162_rn(f.z, f.w);
    }
}

/* --------------------------- f32 -> bf16 convert --------------------------- */
__global__ __launch_bounds__(256) void f2bf_kernel(const float* __restrict__ src,
                                                   __nv_bfloat16* __restrict__ dst,
                                                   int n4) {
    int i = blockIdx.x * blockDim.x + threadIdx.x;
    if (i < n4) {
        float4 f = *(const float4*)(src + (size_t)i*4);
        __nv_bfloat162* d = (__nv_bfloat162*)(dst + (size_t)i*4);
        d[0] = __floats2bfloat162_rn(f.x, f.y);
        d[1] = __floats2bfloat162_rn(f.z, f.w);
    }
}

/* ----------------------------- mma helpers --------------------------------- */
__device__ __forceinline__ void ldmatrix_x4(uint32_t& d0, uint32_t& d1,
                                            uint32_t& d2, uint32_t& d3,
                                            uint32_t addr) {
    asm volatile("ldmatrix.sync.aligned.m8n8.x4.shared.b16 {%0,%1,%2,%3}, [%4];"
                 : "=r"(d0), "=r"(d1), "=r"(d2), "=r"(d3) : "r"(addr));
}
__device__ __forceinline__ void mma_bf16(float* c, const uint32_t* a, const uint32_t* b) {
    asm volatile("mma.sync.aligned.m16n8k16.row.col.f32.bf16.bf16.f32 "
                 "{%0,%1,%2,%3}, {%4,%5,%6,%7}, {%8,%9}, {%0,%1,%2,%3};"
                 : "+f"(c[0]), "+f"(c[1]), "+f"(c[2]), "+f"(c[3])
                 : "r"(a[0]), "r"(a[1]), "r"(a[2]), "r"(a[3]), "r"(b[0]), "r"(b[1]));
}

/* ---------------- bf16 tensor-core GEMM: xw = A @ W^T + bih + bhh ---------- */
#define GBM 128
#define GBN 128
#define GBK 32
#define LDS_W 40

__global__ __launch_bounds__(256) void gemm_bf16_kernel(
        int layer,
        const float* __restrict__ bif, const float* __restrict__ bhf,
        const float* __restrict__ bib, const float* __restrict__ bhb) {
    const int K = layer ? 2*HH : EE;
    const __nv_bfloat16* A = layer ? g_l0h : g_embh;
    int dir = blockIdx.z;
    const __nv_bfloat16* W = g_Wbf + (layer ? (dir ? WOFF_L1B : WOFF_L1F)
                                            : (dir ? WOFF_L0B : WOFF_L0F));
    const float* bi = dir ? bib : bif;
    const float* bh = dir ? bhb : bhf;
    float* out = dir ? g_xw1 : g_xw0;

    __shared__ __nv_bfloat16 As[GBM*LDS_W];
    __shared__ __nv_bfloat16 Bs[GBN*LDS_W];

    int t = threadIdx.x;
    int m0 = blockIdx.y * GBM;
    int n0 = blockIdx.x * GBN;
    int warp = t >> 5, lane = t & 31;
    int wm0 = (warp & 3) * 32;
    int wn0 = (warp >> 2) * 64;

    int lr = t >> 2;
    int lc = (t & 3) * 8;
    const __nv_bfloat16* Ag = A + (size_t)(m0 + lr) * K + lc;
    const __nv_bfloat16* Wg = W + (size_t)(n0 + lr) * K + lc;

    float c[2][8][4];
#pragma unroll
    for (int i = 0; i < 2; i++)
#pragma unroll
        for (int j = 0; j < 8; j++)
#pragma unroll
            for (int q = 0; q < 4; q++) c[i][j][q] = 0.f;

    int arow = (lane & 7) + ((lane >> 3) & 1) * 8;
    int acol = (lane >> 4) * 8;
    int brow = ((lane >> 4) * 8) + (lane & 7);
    int bcol = ((lane >> 3) & 1) * 8;

    uint32_t as_base = (uint32_t)__cvta_generic_to_shared(As);
    uint32_t bs_base = (uint32_t)__cvta_generic_to_shared(Bs);

    const int nk = K / GBK;
    uint4 pa0 = *(const uint4*)(Ag);
    uint4 pa1 = *(const uint4*)(Ag + (size_t)64*K);
    uint4 pb0 = *(const uint4*)(Wg);
    uint4 pb1 = *(const uint4*)(Wg + (size_t)64*K);

    for (int kt = 0; kt < nk; kt++) {
        *(uint4*)(As + lr*LDS_W + lc)        = pa0;
        *(uint4*)(As + (lr+64)*LDS_W + lc)   = pa1;
        *(uint4*)(Bs + lr*LDS_W + lc)        = pb0;
        *(uint4*)(Bs + (lr+64)*LDS_W + lc)   = pb1;
        __syncthreads();
        if (kt + 1 < nk) {
            int ko = (kt + 1) * GBK;
            pa0 = *(const uint4*)(Ag + ko);
            pa1 = *(const uint4*)(Ag + (size_t)64*K + ko);
            pb0 = *(const uint4*)(Wg + ko);
            pb1 = *(const uint4*)(Wg + (size_t)64*K + ko);
        }
#pragma unroll
        for (int ks = 0; ks < GBK; ks += 16) {
            uint32_t a[2][4];
            uint32_t b[8][2];
#pragma unroll
            for (int mt = 0; mt < 2; mt++) {
                uint32_t addr = as_base +
                    (uint32_t)(((wm0 + mt*16 + arow)*LDS_W + ks + acol) * 2);
                ldmatrix_x4(a[mt][0], a[mt][1], a[mt][2], a[mt][3], addr);
            }
#pragma unroll
            for (int p = 0; p < 4; p++) {
                uint32_t addr = bs_base +
                    (uint32_t)(((wn0 + p*16 + brow)*LDS_W + ks + bcol) * 2);
                ldmatrix_x4(b[2*p][0], b[2*p][1], b[2*p+1][0], b[2*p+1][1], addr);
            }
#pragma unroll
            for (int mt = 0; mt < 2; mt++)
#pragma unroll
                for (int nt = 0; nt < 8; nt++)
                    mma_bf16(c[mt][nt], a[mt], b[nt]);
        }
        __syncthreads();
    }

    int g  = lane >> 2;
    int cp = (lane & 3) * 2;
#pragma unroll
    for (int nt = 0; nt < 8; nt++) {
        int n = n0 + wn0 + nt*8 + cp;
        float b0 = bi[n]   + bh[n];
        float b1 = bi[n+1] + bh[n+1];
#pragma unroll
        for (int mt = 0; mt < 2; mt++) {
            int r = m0 + wm0 + mt*16 + g;
            float2 v0 = make_float2(c[mt][nt][0] + b0, c[mt][nt][1] + b1);
            float2 v1 = make_float2(c[mt][nt][2] + b0, c[mt][nt][3] + b1);
            *(float2*)(out + (size_t)r*G4 + n)       = v0;
            *(float2*)(out + (size_t)(r+8)*G4 + n)   = v1;
        }
    }
}

/* ------------------- persistent recurrent scan (bf16 MMA) ------------------ */
#define LW 520                       /* bf16 row stride: 1040B, %128 = 16 -> LDSM conflict-free */
#define GST 34                       /* gate smem row stride (floats) */
#define LSTM_SMEM (32*LW*2*2 + 2*32*GST*4)

__global__ __launch_bounds__(256) void lstm_mma_kernel(int layer) {
    extern __shared__ __align__(16) char smraw[];
    __nv_bfloat16* h_s = (__nv_bfloat16*)smraw;   /* [32][LW] h_{t-1}  */
    __nv_bfloat16* W_s = h_s + 32*LW;             /* [32][LW] Whh slice */
    float* G_s = (float*)(W_s + 32*LW);           /* [2][32][GST] gate partials */

    int t = threadIdx.x;
    int warp = t >> 5, lane = t & 31;
    int dir = blockIdx.x >> 6;
    int hb  = (blockIdx.x & 63) << 3;
    const __nv_bfloat16* Whh = g_Whbf + (layer ? (dir ? WH_L1B : WH_L1F)
                                               : (dir ? WH_L0B : WH_L0F));
    const float* xw = dir ? g_xw1 : g_xw0;
    __nv_bfloat16* hbuf = g_hbuf_bf + dir*2*BB*HH;

    /* stage Whh slice once: W_s[g*8+j][k] <- Whh[g*512 + hb + j][k] */
    {
        int r  = t >> 3;              /* 0..31 */
        int g  = r >> 3, j = r & 7;
        int kq = (t & 7) * 64;
        const uint4* src = (const uint4*)(Whh + (size_t)(g*HH + hb + j)*HH + kq);
        uint4* dst = (uint4*)(W_s + r*LW + kq);
#pragma unroll
        for (int i = 0; i < 8; i++) dst[i] = src[i];
    }

    /* warp tile: 2(M16) x 2(N16) x 2(K256) */
    int mb = (warp & 1) * 16;
    int nb = ((warp >> 1) & 1) * 16;
    int kb = (warp >> 2) * 256;
    float* Gk = G_s + (warp >> 2) * 32 * GST;

    int arow = (lane & 7) + ((lane >> 3) & 1) * 8;
    int acol = (lane >> 4) * 8;
    int brow = ((lane >> 4) * 8) + (lane & 7);
    int bcol = ((lane >> 3) & 1) * 8;
    uint32_t hs_base = (uint32_t)__cvta_generic_to_shared(h_s);
    uint32_t ws_base = (uint32_t)__cvta_generic_to_shared(W_s);

    /* gate-math mapping: thread -> (batch gb, local hcol gj) */
    int gb = t >> 3;
    int gj = t & 7;

    float c = 0.f;

    for (int it = 0; it < TT; it++) {
        int tstep = dir ? (TT - 1 - it) : it;

        /* prefetch xw for this thread's gate math (independent of h) */
        const float* xp = xw + (size_t)(tstep*32 + gb)*G4 + hb + gj;
        float x0 = __ldg(xp + 0*HH);
        float x1 = __ldg(xp + 1*HH);
        float x2 = __ldg(xp + 2*HH);
        float x3 = __ldg(xp + 3*HH);

        /* stage h_{t-1} (32x512 bf16 = 32KB) */
        {
            int r  = t >> 3;
            int kq = (t & 7) * 64;
            uint4* dst = (uint4*)(h_s + r*LW + kq);
            if (it == 0) {
                uint4 z = make_uint4(0u,0u,0u,0u);
#pragma unroll
                for (int i = 0; i < 8; i++) dst[i] = z;
            } else {
                const uint4* src = (const uint4*)(hbuf + ((it & 1) ? BB*HH : 0) + r*HH + kq);
#pragma unroll
                for (int i = 0; i < 8; i++) dst[i] = __ldcg(src + i);
            }
        }
        __syncthreads();

        float acc[2][4];
#pragma unroll
        for (int nt = 0; nt < 2; nt++)
#pragma unroll
            for (int q = 0; q < 4; q++) acc[nt][q] = 0.f;

#pragma unroll
        for (int ks = 0; ks < 16; ks++) {
            uint32_t a[4], b0[2], b1[2];
            uint32_t addrA = hs_base + (uint32_t)(((mb + arow)*LW + kb + ks*16 + acol) * 2);
            ldmatrix_x4(a[0], a[1], a[2], a[3], addrA);
            uint32_t addrB = ws_base + (uint32_t)(((nb + brow)*LW + kb + ks*16 + bcol) * 2);
            ldmatrix_x4(b0[0], b0[1], b1[0], b1[1], addrB);
            mma_bf16(acc[0], a, b0);
            mma_bf16(acc[1], a, b1);
        }

        /* C fragments -> gate smem (K-split partials) */
        {
            int g  = lane >> 2;
            int cp = (lane & 3) * 2;
#pragma unroll
            for (int nt = 0; nt < 2; nt++) {
                *(float2*)(Gk + (mb + g)*GST     + nb + nt*8 + cp) = make_float2(acc[nt][0], acc[nt][1]);
                *(float2*)(Gk + (mb + g + 8)*GST + nb + nt*8 + cp) = make_float2(acc[nt][2], acc[nt][3]);
            }
        }
        __syncthreads();

        /* gate math: thread (gb, gj); torch gate order i, f, g, o */
        {
            float a0 = x0 + G_s[gb*GST + 0*8 + gj] + G_s[32*GST + gb*GST + 0*8 + gj];
            float a1 = x1 + G_s[gb*GST + 1*8 + gj] + G_s[32*GST + gb*GST + 1*8 + gj];
            float a2 = x2 + G_s[gb*GST + 2*8 + gj] + G_s[32*GST + gb*GST + 2*8 + gj];
            float a3 = x3 + G_s[gb*GST + 3*8 + gj] + G_s[32*GST + gb*GST + 3*8 + gj];
            float ig = sigmoid_fast(a0);
            float fg = sigmoid_fast(a1);
            float gg = tanh_fast(a2);
            float og = sigmoid_fast(a3);
            c = fg*c + ig*gg;
            float hv = og * tanh_fast(c);
            __nv_bfloat16 hbv = __float2bfloat16(hv);
            hbuf[(((it + 1) & 1) ? BB*HH : 0) + gb*HH + hb + gj] = hbv;
            if (layer == 0)
                g_l0h[(size_t)(tstep*32 + gb)*(2*HH) + dir*HH + hb + gj] = hbv;
            else
                g_l1out[(size_t)(tstep*32 + gb)*(2*HH) + dir*HH + hb + gj] = hv;
        }
        dir_sync(dir);
    }
}

/* --------------------- classifier + log_softmax + transpose ---------------- */
__global__ __launch_bounds__(256) void cls_kernel(const float* __restrict__ truth,
        const int* __restrict__ tf, const float* __restrict__ Wc,
        const float* __restrict__ bc, float* __restrict__ out) {
    __shared__ float Fs[64*68];
    __shared__ float Ws[32*68];
    __shared__ float Ls[64*33];
    __shared__ float lse[64];

    int t  = threadIdx.x;
    int p0 = blockIdx.x * 64;
    int p  = t & 63, cg = t >> 6;

    float acc[8];
#pragma unroll
    for (int j = 0; j < 8; j++) acc[j] = 0.f;

    for (int kc = 0; kc < 2*HH; kc += 64) {
        __syncthreads();
#pragma unroll
        for (int pass = 0; pass < 4; pass++) {
            int pp = pass*16 + (t >> 4);
            int kq = (t & 15) * 4;
            *(float4*)(Fs + pp*68 + kq) =
                *(const float4*)(g_l1out + (size_t)(p0 + pp)*(2*HH) + kc + kq);
        }
        {
            int cc = t >> 3, j0 = (t & 7) * 8;
            const float* src = Wc + (size_t)cc*(2*HH + 1) + 1 + kc + j0;
            float* dst = Ws + cc*68 + j0;
#pragma unroll
            for (int i = 0; i < 8; i++) dst[i] = src[i];
        }
        __syncthreads();
#pragma unroll
        for (int kk = 0; kk < 16; kk++) {
            float4 f = *(const float4*)(Fs + p*68 + kk*4);
#pragma unroll
            for (int j = 0; j < 8; j++) {
                float4 wv = *(const float4*)(Ws + (cg*8 + j)*68 + kk*4);
                acc[j] = fmaf(f.x,wv.x, fmaf(f.y,wv.y, fmaf(f.z,wv.z, fmaf(f.w,wv.w, acc[j]))));
            }
        }
    }

    int mp = p0 + p;
    int b  = mp & 31;
    int tt = mp >> 5;
    float past = 0.f;
    if (tt > 0 && tf[0] != 0) past = truth[b*TT + tt - 1];
#pragma unroll
    for (int j = 0; j < 8; j++) {
        int cc = cg*8 + j;
        acc[j] += bc[cc] + past * Wc[(size_t)cc*(2*HH + 1)];
        Ls[p*33 + cc] = acc[j];
    }
    __syncthreads();
    if (t < 64) {
        float m = -1e30f;
#pragma unroll
        for (int cc = 0; cc < CC; cc++) m = fmaxf(m, Ls[t*33 + cc]);
        float s = 0.f;
#pragma unroll
        for (int cc = 0; cc < CC; cc++) s += expf(Ls[t*33 + cc] - m);
        lse[t] = m + logf(s);
    }
    __syncthreads();
    {
        float l = lse[p];
#pragma unroll
        for (int j = 0; j < 8; j++) {
            int cc = cg*8 + j;
            out[(size_t)b*CC*TT + (size_t)cc*TT + tt] = Ls[p*33 + cc] - l;
        }
    }
}

/* ------------------------------- launch ------------------------------------ */
extern "C" void kernel_launch(void* const* d_in, const int* in_sizes, int n_in,
                              void* d_out, int out_size) {
    (void)in_sizes; (void)n_in; (void)out_size;
    const int*   x     = (const int*)  d_in[0];
    const float* truth = (const float*)d_in[1];
    const int*   tf    = (const int*)  d_in[2];
    const float* emb   = (const float*)d_in[3];
    const float* Wih0f = (const float*)d_in[4];
    const float* Whh0f = (const float*)d_in[5];
    const float* bih0f = (const float*)d_in[6];
    const float* bhh0f = (const float*)d_in[7];
    const float* Wih0b = (const float*)d_in[8];
    const float* Whh0b = (const float*)d_in[9];
    const float* bih0b = (const float*)d_in[10];
    const float* bhh0b = (const float*)d_in[11];
    const float* Wih1f = (const float*)d_in[12];
    const float* Whh1f = (const float*)d_in[13];
    const float* bih1f = (const float*)d_in[14];
    const float* bhh1f = (const float*)d_in[15];
    const float* Wih1b = (const float*)d_in[16];
    const float* Whh1b = (const float*)d_in[17];
    const float* bih1b = (const float*)d_in[18];
    const float* bhh1b = (const float*)d_in[19];
    const float* Wc    = (const float*)d_in[20];
    const float* bc    = (const float*)d_in[21];
    float* out = (float*)d_out;

    cudaFuncSetAttribute(lstm_mma_kernel,
                         cudaFuncAttributeMaxDynamicSharedMemorySize, LSTM_SMEM);

    __nv_bfloat16* wbf = nullptr;
    cudaGetSymbolAddress((void**)&wbf, g_Wbf);
    __nv_bfloat16* whbf = nullptr;
    cudaGetSymbolAddress((void**)&whbf, g_Whbf);

    embed_kernel<<<MM/8, 256>>>(x, emb);

    /* convert Wih + Whh matrices to bf16 */
    {
        int n0 = G4*EE  / 4;   /* 2048*512/4  */
        int n1 = G4*2*HH / 4;  /* 2048*1024/4 */
        int nh = G4*HH  / 4;   /* 2048*512/4  */
        f2bf_kernel<<<(n0+255)/256, 256>>>(Wih0f, wbf + WOFF_L0F, n0);
        f2bf_kernel<<<(n0+255)/256, 256>>>(Wih0b, wbf + WOFF_L0B, n0);
        f2bf_kernel<<<(n1+255)/256, 256>>>(Wih1f, wbf + WOFF_L1F, n1);
        f2bf_kernel<<<(n1+255)/256, 256>>>(Wih1b, wbf + WOFF_L1B, n1);
        f2bf_kernel<<<(nh+255)/256, 256>>>(Whh0f, whbf + WH_L0F, nh);
        f2bf_kernel<<<(nh+255)/256, 256>>>(Whh0b, whbf + WH_L0B, nh);
        f2bf_kernel<<<(nh+255)/256, 256>>>(Whh1f, whbf + WH_L1F, nh);
        f2bf_kernel<<<(nh+255)/256, 256>>>(Whh1b, whbf + WH_L1B, nh);
    }

    dim3 g0(G4/GBN, MM/GBM, 2);   /* 16 x 128 x 2 */
    gemm_bf16_kernel<<<g0, 256>>>(0, bih0f, bhh0f, bih0b, bhh0b);
    lstm_mma_kernel<<<NBLK, 256, LSTM_SMEM>>>(0);

    gemm_bf16_kernel<<<g0, 256>>>(1, bih1f, bhh1f, bih1b, bhh1b);
    lstm_mma_kernel<<<NBLK, 256, LSTM_SMEM>>>(1);

    cls_kernel<<<MM/64, 256>>>(truth, tf, Wc, bc, out);
}

// round 12
// speedup vs baseline: 1.1831x; 1.0219x over previous
#include <cuda_runtime.h>
#include <cuda_bf16.h>
#include <math.h>
#include <stdint.h>

#define BB 32
#define TT 512
#define EE 512
#define HH 512
#define CC 32
#define MM (BB*TT)        /* 16384 token positions, m' = t*32 + b */
#define G4 (4*HH)         /* 2048 gate columns per direction */
#define NBLK 64           /* persistent LSTM grid: 32 blocks per direction */
#define NB2  (NBLK/2)

/* ------------------------ scratch (static device memory) ------------------- */
__device__ __nv_bfloat16 g_embh[(size_t)MM*EE];    /* layer0 GEMM input (bf16) */
__device__ __nv_bfloat16 g_l0h[(size_t)MM*2*HH];   /* layer0 output     (bf16) */
__device__ __nv_bfloat16 g_Wbf[2*(size_t)G4*EE + 2*(size_t)G4*2*HH]; /* Wih bf16 */
__device__ __nv_bfloat16 g_Whbf[4*(size_t)G4*HH];  /* Whh bf16 (4 matrices)    */
__device__ float g_xw0[(size_t)MM*G4];             /* xw forward  [m'][2048]   */
__device__ float g_xw1[(size_t)MM*G4];             /* xw backward [m'][2048]   */
__device__ float g_l1out[(size_t)MM*2*HH];         /* layer1 output [m'][1024] */
__device__ __nv_bfloat16 g_hbuf_bf[2*2*BB*HH];     /* [dir][parity][b][h] bf16 */
__device__ unsigned g_bar_cnt[2] = {0, 0};
__device__ unsigned g_bar_gen[2] = {0, 0};

/* Wbf offsets (Wih) */
#define WOFF_L0F ((size_t)0)
#define WOFF_L0B ((size_t)G4*EE)
#define WOFF_L1F ((size_t)2*G4*EE)
#define WOFF_L1B ((size_t)2*G4*EE + (size_t)G4*2*HH)
/* Whbf offsets (Whh) */
#define WH_L0F ((size_t)0)
#define WH_L0B ((size_t)G4*HH)
#define WH_L1F ((size_t)2*G4*HH)
#define WH_L1B ((size_t)3*G4*HH)

/* ------------------ acq/rel atomic helpers (gpu scope) --------------------- */
__device__ __forceinline__ unsigned ld_acq(const unsigned* p) {
    unsigned v;
    asm volatile("ld.acquire.gpu.global.u32 %0, [%1];" : "=r"(v) : "l"(p) : "memory");
    return v;
}
__device__ __forceinline__ unsigned atom_add_acqrel(unsigned* p, unsigned v) {
    unsigned old;
    asm volatile("atom.acq_rel.gpu.global.add.u32 %0, [%1], %2;"
                 : "=r"(old) : "l"(p), "r"(v) : "memory");
    return old;
}
__device__ __forceinline__ void red_add_rel(unsigned* p, unsigned v) {
    asm volatile("red.release.gpu.global.add.u32 [%0], %1;" :: "l"(p), "r"(v) : "memory");
}
__device__ __forceinline__ void st_rlx(unsigned* p, unsigned v) {
    asm volatile("st.relaxed.gpu.global.u32 [%0], %1;" :: "l"(p), "r"(v) : "memory");
}

/* --------------------- per-direction grid barrier (32 blocks) -------------- */
__device__ __forceinline__ void dir_sync(int dir) {
    __syncthreads();
    if (threadIdx.x == 0) {
        unsigned gen = ld_acq(&g_bar_gen[dir]);
        unsigned prev = atom_add_acqrel(&g_bar_cnt[dir], 1u);
        if (prev == NB2 - 1) {
            st_rlx(&g_bar_cnt[dir], 0u);
            red_add_rel(&g_bar_gen[dir], 1u);
        }
        while (ld_acq(&g_bar_gen[dir]) == gen) { }
    }
    __syncthreads();
}

/* --------------------------- fast activations ------------------------------ */
__device__ __forceinline__ float tanh_fast(float x) {
    float y;
    asm("tanh.approx.f32 %0, %1;" : "=f"(y) : "f"(x));
    return y;
}
__device__ __forceinline__ float sigmoid_fast(float x) {
    return fmaf(tanh_fast(0.5f * x), 0.5f, 0.5f);
}

/* ------------------------------ embedding (f32 -> bf16) -------------------- */
__global__ __launch_bounds__(256) void embed_kernel(const int* __restrict__ x,
                                                    const float* __restrict__ emb) {
    int gid  = blockIdx.x * blockDim.x + threadIdx.x;
    int mp   = gid >> 5;
    int lane = gid & 31;
    int b  = mp & 31;
    int tt = mp >> 5;
    int v  = x[b*TT + tt];
    const float4* src = (const float4*)(emb + (size_t)v*EE);
    __nv_bfloat162* dst = (__nv_bfloat162*)(g_embh + (size_t)mp*EE);
#pragma unroll
    for (int r = 0; r < EE/128; r++) {
        float4 f = src[r*32 + lane];
        dst[(r*32 + lane)*2 + 0] = __floats2bfloat162_rn(f.x, f.y);
        dst[(r*32 + lane)*2 + 1] = __floats2bfloat162_rn(f.z, f.w);
    }
}

/* ------------------ single-launch f32 -> bf16 convert (all 8 W) ------------ */
__global__ __launch_bounds__(256) void conv_all_kernel(
        const float* __restrict__ s0, const float* __restrict__ s1,
        const float* __restrict__ s2, const float* __restrict__ s3,
        const float* __restrict__ s4, const float* __restrict__ s5,
        const float* __restrict__ s6, const float* __restrict__ s7) {
    int z = blockIdx.y;
    const float* src;
    __nv_bfloat16* dst;
    int n4;
    switch (z) {
        case 0: src = s0; dst = g_Wbf  + WOFF_L0F; n4 = G4*EE/4;   break;
        case 1: src = s1; dst = g_Wbf  + WOFF_L0B; n4 = G4*EE/4;   break;
        case 2: src = s2; dst = g_Wbf  + WOFF_L1F; n4 = G4*2*HH/4; break;
        case 3: src = s3; dst = g_Wbf  + WOFF_L1B; n4 = G4*2*HH/4; break;
        case 4: src = s4; dst = g_Whbf + WH_L0F;   n4 = G4*HH/4;   break;
        case 5: src = s5; dst = g_Whbf + WH_L0B;   n4 = G4*HH/4;   break;
        case 6: src = s6; dst = g_Whbf + WH_L1F;   n4 = G4*HH/4;   break;
        default: src = s7; dst = g_Whbf + WH_L1B;  n4 = G4*HH/4;   break;
    }
    int i = blockIdx.x * blockDim.x + threadIdx.x;
    if (i < n4) {
        float4 f = *(const float4*)(src + (size_t)i*4);
        __nv_bfloat162* d = (__nv_bfloat162*)(dst + (size_t)i*4);
        d[0] = __floats2bfloat162_rn(f.x, f.y);
        d[1] = __floats2bfloat162_rn(f.z, f.w);
    }
}

/* ----------------------------- mma helpers --------------------------------- */
__device__ __forceinline__ void ldmatrix_x4(uint32_t& d0, uint32_t& d1,
                                            uint32_t& d2, uint32_t& d3,
                                            uint32_t addr) {
    asm volatile("ldmatrix.sync.aligned.m8n8.x4.shared.b16 {%0,%1,%2,%3}, [%4];"
                 : "=r"(d0), "=r"(d1), "=r"(d2), "=r"(d3) : "r"(addr));
}
__device__ __forceinline__ void mma_bf16(float* c, const uint32_t* a, const uint32_t* b) {
    asm volatile("mma.sync.aligned.m16n8k16.row.col.f32.bf16.bf16.f32 "
                 "{%0,%1,%2,%3}, {%4,%5,%6,%7}, {%8,%9}, {%0,%1,%2,%3};"
                 : "+f"(c[0]), "+f"(c[1]), "+f"(c[2]), "+f"(c[3])
                 : "r"(a[0]), "r"(a[1]), "r"(a[2]), "r"(a[3]), "r"(b[0]), "r"(b[1]));
}

/* ---------------- bf16 tensor-core GEMM: xw = A @ W^T + bih + bhh ---------- */
#define GBM 128
#define GBN 128
#define GBK 32
#define LDS_W 40

__global__ __launch_bounds__(256) void gemm_bf16_kernel(
        int layer,
        const float* __restrict__ bif, const float* __restrict__ bhf,
        const float* __restrict__ bib, const float* __restrict__ bhb) {
    const int K = layer ? 2*HH : EE;
    const __nv_bfloat16* A = layer ? g_l0h : g_embh;
    int dir = blockIdx.z;
    const __nv_bfloat16* W = g_Wbf + (layer ? (dir ? WOFF_L1B : WOFF_L1F)
                                            : (dir ? WOFF_L0B : WOFF_L0F));
    const float* bi = dir ? bib : bif;
    const float* bh = dir ? bhb : bhf;
    float* out = dir ? g_xw1 : g_xw0;

    __shared__ __nv_bfloat16 As[GBM*LDS_W];
    __shared__ __nv_bfloat16 Bs[GBN*LDS_W];

    int t = threadIdx.x;
    int m0 = blockIdx.y * GBM;
    int n0 = blockIdx.x * GBN;
    int warp = t >> 5, lane = t & 31;
    int wm0 = (warp & 3) * 32;
    int wn0 = (warp >> 2) * 64;

    int lr = t >> 2;
    int lc = (t & 3) * 8;
    const __nv_bfloat16* Ag = A + (size_t)(m0 + lr) * K + lc;
    const __nv_bfloat16* Wg = W + (size_t)(n0 + lr) * K + lc;

    float c[2][8][4];
#pragma unroll
    for (int i = 0; i < 2; i++)
#pragma unroll
        for (int j = 0; j < 8; j++)
#pragma unroll
            for (int q = 0; q < 4; q++) c[i][j][q] = 0.f;

    int arow = (lane & 7) + ((lane >> 3) & 1) * 8;
    int acol = (lane >> 4) * 8;
    int brow = ((lane >> 4) * 8) + (lane & 7);
    int bcol = ((lane >> 3) & 1) * 8;

    uint32_t as_base = (uint32_t)__cvta_generic_to_shared(As);
    uint32_t bs_base = (uint32_t)__cvta_generic_to_shared(Bs);

    const int nk = K / GBK;
    uint4 pa0 = *(const uint4*)(Ag);
    uint4 pa1 = *(const uint4*)(Ag + (size_t)64*K);
    uint4 pb0 = *(const uint4*)(Wg);
    uint4 pb1 = *(const uint4*)(Wg + (size_t)64*K);

    for (int kt = 0; kt < nk; kt++) {
        *(uint4*)(As + lr*LDS_W + lc)        = pa0;
        *(uint4*)(As + (lr+64)*LDS_W + lc)   = pa1;
        *(uint4*)(Bs + lr*LDS_W + lc)        = pb0;
        *(uint4*)(Bs + (lr+64)*LDS_W + lc)   = pb1;
        __syncthreads();
        if (kt + 1 < nk) {
            int ko = (kt + 1) * GBK;
            pa0 = *(const uint4*)(Ag + ko);
            pa1 = *(const uint4*)(Ag + (size_t)64*K + ko);
            pb0 = *(const uint4*)(Wg + ko);
            pb1 = *(const uint4*)(Wg + (size_t)64*K + ko);
        }
#pragma unroll
        for (int ks = 0; ks < GBK; ks += 16) {
            uint32_t a[2][4];
            uint32_t b[8][2];
#pragma unroll
            for (int mt = 0; mt < 2; mt++) {
                uint32_t addr = as_base +
                    (uint32_t)(((wm0 + mt*16 + arow)*LDS_W + ks + acol) * 2);
                ldmatrix_x4(a[mt][0], a[mt][1], a[mt][2], a[mt][3], addr);
            }
#pragma unroll
            for (int p = 0; p < 4; p++) {
                uint32_t addr = bs_base +
                    (uint32_t)(((wn0 + p*16 + brow)*LDS_W + ks + bcol) * 2);
                ldmatrix_x4(b[2*p][0], b[2*p][1], b[2*p+1][0], b[2*p+1][1], addr);
            }
#pragma unroll
            for (int mt = 0; mt < 2; mt++)
#pragma unroll
                for (int nt = 0; nt < 8; nt++)
                    mma_bf16(c[mt][nt], a[mt], b[nt]);
        }
        __syncthreads();
    }

    int g  = lane >> 2;
    int cp = (lane & 3) * 2;
#pragma unroll
    for (int nt = 0; nt < 8; nt++) {
        int n = n0 + wn0 + nt*8 + cp;
        float b0 = bi[n]   + bh[n];
        float b1 = bi[n+1] + bh[n+1];
#pragma unroll
        for (int mt = 0; mt < 2; mt++) {
            int r = m0 + wm0 + mt*16 + g;
            float2 v0 = make_float2(c[mt][nt][0] + b0, c[mt][nt][1] + b1);
            float2 v1 = make_float2(c[mt][nt][2] + b0, c[mt][nt][3] + b1);
            *(float2*)(out + (size_t)r*G4 + n)       = v0;
            *(float2*)(out + (size_t)(r+8)*G4 + n)   = v1;
        }
    }
}

/* ------------------- persistent recurrent scan (bf16 MMA) ------------------
 * 32 blocks per direction; each block owns 16 h-columns (64 gate rows).
 * Warp tile: 2(M16) x 2(N32) x 2(K256).                                     */
#define LW 520                       /* bf16 row stride */
#define GST 66                       /* gate smem row stride (floats) */
#define LSTM_SMEM ((32*LW + 64*LW)*2 + 2*32*GST*4)

__global__ __launch_bounds__(256) void lstm_mma_kernel(int layer) {
    extern __shared__ __align__(16) char smraw[];
    __nv_bfloat16* h_s = (__nv_bfloat16*)smraw;   /* [32][LW] h_{t-1}        */
    __nv_bfloat16* W_s = h_s + 32*LW;             /* [64][LW] Whh slice      */
    float* G_s = (float*)(W_s + 64*LW);           /* [2][32][GST] partials   */

    int t = threadIdx.x;
    int warp = t >> 5, lane = t & 31;
    int dir = blockIdx.x >> 5;
    int hb  = (blockIdx.x & 31) << 4;             /* 16 h-cols per block */
    const __nv_bfloat16* Whh = g_Whbf + (layer ? (dir ? WH_L1B : WH_L1F)
                                               : (dir ? WH_L0B : WH_L0F));
    const float* xw = dir ? g_xw1 : g_xw0;
    __nv_bfloat16* hbuf = g_hbuf_bf + dir*2*BB*HH;

    /* stage Whh slice once: W_s[g*16+j][k] <- Whh[g*512 + hb + j][k]
       64 rows x 512 bf16; 256 threads, each 1/4 row (128 bf16) */
    {
        int r  = t >> 2;              /* 0..63 */
        int g  = r >> 4, j = r & 15;
        int kq = (t & 3) * 128;
        const uint4* src = (const uint4*)(Whh + (size_t)(g*HH + hb + j)*HH + kq);
        uint4* dst = (uint4*)(W_s + r*LW + kq);
#pragma unroll
        for (int i = 0; i < 16; i++) dst[i] = src[i];
    }

    /* warp tile: mb in {0,16}, nb in {0,32}, kb in {0,256} */
    int mb = (warp & 1) * 16;
    int nb = ((warp >> 1) & 1) * 32;
    int kb = (warp >> 2) * 256;
    float* Gk = G_s + (warp >> 2) * 32 * GST;

    int arow = (lane & 7) + ((lane >> 3) & 1) * 8;
    int acol = (lane >> 4) * 8;
    int brow = ((lane >> 4) * 8) + (lane & 7);
    int bcol = ((lane >> 3) & 1) * 8;
    uint32_t hs_base = (uint32_t)__cvta_generic_to_shared(h_s);
    uint32_t ws_base = (uint32_t)__cvta_generic_to_shared(W_s);

    /* gate math mapping: thread -> (batch gb, 2 h-cols gj0, gj0+1) */
    int gb  = t >> 3;
    int gj0 = (t & 7) * 2;

    float c0 = 0.f, c1 = 0.f;

    for (int it = 0; it < TT; it++) {
        int tstep = dir ? (TT - 1 - it) : it;

        /* prefetch xw pairs for this thread's gate math */
        const float* xp = xw + (size_t)(tstep*32 + gb)*G4 + hb + gj0;
        float2 x0 = *(const float2*)(xp + 0*HH);
        float2 x1 = *(const float2*)(xp + 1*HH);
        float2 x2 = *(const float2*)(xp + 2*HH);
        float2 x3 = *(const float2*)(xp + 3*HH);

        /* stage h_{t-1} (32x512 bf16 = 32KB) */
        {
            int r  = t >> 3;
            int kq = (t & 7) * 64;
            uint4* dst = (uint4*)(h_s + r*LW + kq);
            if (it == 0) {
                uint4 z = make_uint4(0u,0u,0u,0u);
#pragma unroll
                for (int i = 0; i < 8; i++) dst[i] = z;
            } else {
                const uint4* src = (const uint4*)(hbuf + ((it & 1) ? BB*HH : 0) + r*HH + kq);
#pragma unroll
                for (int i = 0; i < 8; i++) dst[i] = __ldcg(src + i);
            }
        }
        __syncthreads();

        float acc[4][4];
#pragma unroll
        for (int nt = 0; nt < 4; nt++)
#pragma unroll
            for (int q = 0; q < 4; q++) acc[nt][q] = 0.f;

#pragma unroll
        for (int ks = 0; ks < 16; ks++) {
            uint32_t a[4], b0[2], b1[2], b2[2], b3[2];
            uint32_t addrA = hs_base + (uint32_t)(((mb + arow)*LW + kb + ks*16 + acol) * 2);
            ldmatrix_x4(a[0], a[1], a[2], a[3], addrA);
            uint32_t addrB0 = ws_base + (uint32_t)(((nb + brow)*LW + kb + ks*16 + bcol) * 2);
            ldmatrix_x4(b0[0], b0[1], b1[0], b1[1], addrB0);
            uint32_t addrB1 = ws_base + (uint32_t)(((nb + 16 + brow)*LW + kb + ks*16 + bcol) * 2);
            ldmatrix_x4(b2[0], b2[1], b3[0], b3[1], addrB1);
            mma_bf16(acc[0], a, b0);
            mma_bf16(acc[1], a, b1);
            mma_bf16(acc[2], a, b2);
            mma_bf16(acc[3], a, b3);
        }

        /* C fragments -> gate smem (K-split partials) */
        {
            int g  = lane >> 2;
            int cp = (lane & 3) * 2;
#pragma unroll
            for (int nt = 0; nt < 4; nt++) {
                *(float2*)(Gk + (mb + g)*GST     + nb + nt*8 + cp) = make_float2(acc[nt][0], acc[nt][1]);
                *(float2*)(Gk + (mb + g + 8)*GST + nb + nt*8 + cp) = make_float2(acc[nt][2], acc[nt][3]);
            }
        }
        __syncthreads();

        /* gate math: thread (gb, gj0..gj0+1); torch gate order i, f, g, o */
        {
            float2 p0 = *(const float2*)(G_s + gb*GST + 0*16 + gj0);
            float2 p1 = *(const float2*)(G_s + gb*GST + 1*16 + gj0);
            float2 p2 = *(const float2*)(G_s + gb*GST + 2*16 + gj0);
            float2 p3 = *(const float2*)(G_s + gb*GST + 3*16 + gj0);
            float2 q0 = *(const float2*)(G_s + 32*GST + gb*GST + 0*16 + gj0);
            float2 q1 = *(const float2*)(G_s + 32*GST + gb*GST + 1*16 + gj0);
            float2 q2 = *(const float2*)(G_s + 32*GST + gb*GST + 2*16 + gj0);
            float2 q3 = *(const float2*)(G_s + 32*GST + gb*GST + 3*16 + gj0);

            float a0a = x0.x + p0.x + q0.x, a0b = x0.y + p0.y + q0.y;
            float a1a = x1.x + p1.x + q1.x, a1b = x1.y + p1.y + q1.y;
            float a2a = x2.x + p2.x + q2.x, a2b = x2.y + p2.y + q2.y;
            float a3a = x3.x + p3.x + q3.x, a3b = x3.y + p3.y + q3.y;

            float iga = sigmoid_fast(a0a), igb = sigmoid_fast(a0b);
            float fga = sigmoid_fast(a1a), fgb = sigmoid_fast(a1b);
            float gga = tanh_fast(a2a),    ggb = tanh_fast(a2b);
            float oga = sigmoid_fast(a3a), ogb = sigmoid_fast(a3b);
            c0 = fga*c0 + iga*gga;
            c1 = fgb*c1 + igb*ggb;
            float hva = oga * tanh_fast(c0);
            float hvb = ogb * tanh_fast(c1);
            __nv_bfloat162 hb2 = __floats2bfloat162_rn(hva, hvb);

            *(__nv_bfloat162*)(hbuf + (((it + 1) & 1) ? BB*HH : 0) + gb*HH + hb + gj0) = hb2;
            if (layer == 0)
                *(__nv_bfloat162*)(g_l0h + (size_t)(tstep*32 + gb)*(2*HH) + dir*HH + hb + gj0) = hb2;
            else
                *(float2*)(g_l1out + (size_t)(tstep*32 + gb)*(2*HH) + dir*HH + hb + gj0) =
                    make_float2(hva, hvb);
        }
        dir_sync(dir);
    }
}

/* --------------------- classifier + log_softmax + transpose ---------------- */
__global__ __launch_bounds__(256) void cls_kernel(const float* __restrict__ truth,
        const int* __restrict__ tf, const float* __restrict__ Wc,
        const float* __restrict__ bc, float* __restrict__ out) {
    __shared__ float Fs[64*68];
    __shared__ float Ws[32*68];
    __shared__ float Ls[64*33];
    __shared__ float lse[64];

    int t  = threadIdx.x;
    int p0 = blockIdx.x * 64;
    int p  = t & 63, cg = t >> 6;

    float acc[8];
#pragma unroll
    for (int j = 0; j < 8; j++) acc[j] = 0.f;

    for (int kc = 0; kc < 2*HH; kc += 64) {
        __syncthreads();
#pragma unroll
        for (int pass = 0; pass < 4; pass++) {
            int pp = pass*16 + (t >> 4);
            int kq = (t & 15) * 4;
            *(float4*)(Fs + pp*68 + kq) =
                *(const float4*)(g_l1out + (size_t)(p0 + pp)*(2*HH) + kc + kq);
        }
        {
            int cc = t >> 3, j0 = (t & 7) * 8;
            const float* src = Wc + (size_t)cc*(2*HH + 1) + 1 + kc + j0;
            float* dst = Ws + cc*68 + j0;
#pragma unroll
            for (int i = 0; i < 8; i++) dst[i] = src[i];
        }
        __syncthreads();
#pragma unroll
        for (int kk = 0; kk < 16; kk++) {
            float4 f = *(const float4*)(Fs + p*68 + kk*4);
#pragma unroll
            for (int j = 0; j < 8; j++) {
                float4 wv = *(const float4*)(Ws + (cg*8 + j)*68 + kk*4);
                acc[j] = fmaf(f.x,wv.x, fmaf(f.y,wv.y, fmaf(f.z,wv.z, fmaf(f.w,wv.w, acc[j]))));
            }
        }
    }

    int mp = p0 + p;
    int b  = mp & 31;
    int tt = mp >> 5;
    float past = 0.f;
    if (tt > 0 && tf[0] != 0) past = truth[b*TT + tt - 1];
#pragma unroll
    for (int j = 0; j < 8; j++) {
        int cc = cg*8 + j;
        acc[j] += bc[cc] + past * Wc[(size_t)cc*(2*HH + 1)];
        Ls[p*33 + cc] = acc[j];
    }
    __syncthreads();
    if (t < 64) {
        float m = -1e30f;
#pragma unroll
        for (int cc = 0; cc < CC; cc++) m = fmaxf(m, Ls[t*33 + cc]);
        float s = 0.f;
#pragma unroll
        for (int cc = 0; cc < CC; cc++) s += expf(Ls[t*33 + cc] - m);
        lse[t] = m + logf(s);
    }
    __syncthreads();
    {
        float l = lse[p];
#pragma unroll
        for (int j = 0; j < 8; j++) {
            int cc = cg*8 + j;
            out[(size_t)b*CC*TT + (size_t)cc*TT + tt] = Ls[p*33 + cc] - l;
        }
    }
}

/* ------------------------------- launch ------------------------------------ */
extern "C" void kernel_launch(void* const* d_in, const int* in_sizes, int n_in,
                              void* d_out, int out_size) {
    (void)in_sizes; (void)n_in; (void)out_size;
    const int*   x     = (const int*)  d_in[0];
    const float* truth = (const float*)d_in[1];
    const int*   tf    = (const int*)  d_in[2];
    const float* emb   = (const float*)d_in[3];
    const float* Wih0f = (const float*)d_in[4];
    const float* Whh0f = (const float*)d_in[5];
    const float* bih0f = (const float*)d_in[6];
    const float* bhh0f = (const float*)d_in[7];
    const float* Wih0b = (const float*)d_in[8];
    const float* Whh0b = (const float*)d_in[9];
    const float* bih0b = (const float*)d_in[10];
    const float* bhh0b = (const float*)d_in[11];
    const float* Wih1f = (const float*)d_in[12];
    const float* Whh1f = (const float*)d_in[13];
    const float* bih1f = (const float*)d_in[14];
    const float* bhh1f = (const float*)d_in[15];
    const float* Wih1b = (const float*)d_in[16];
    const float* Whh1b = (const float*)d_in[17];
    const float* bih1b = (const float*)d_in[18];
    const float* bhh1b = (const float*)d_in[19];
    const float* Wc    = (const float*)d_in[20];
    const float* bc    = (const float*)d_in[21];
    float* out = (float*)d_out;

    cudaFuncSetAttribute(lstm_mma_kernel,
                         cudaFuncAttributeMaxDynamicSharedMemorySize, LSTM_SMEM);

    /* launch order fixes ncu -s 5 -c 1 onto lstm1 (launch #6):
       conv(1) embed(2) gemm0(3) lstm0(4) gemm1(5) lstm1(6) cls(7) */
    dim3 gc(2048, 8);
    conv_all_kernel<<<gc, 256>>>(Wih0f, Wih0b, Wih1f, Wih1b,
                                 Whh0f, Whh0b, Whh1f, Whh1b);

    embed_kernel<<<MM/8, 256>>>(x, emb);

    dim3 g0(G4/GBN, MM/GBM, 2);   /* 16 x 128 x 2 */
    gemm_bf16_kernel<<<g0, 256>>>(0, bih0f, bhh0f, bih0b, bhh0b);
    lstm_mma_kernel<<<NBLK, 256, LSTM_SMEM>>>(0);

    gemm_bf16_kernel<<<g0, 256>>>(1, bih1f, bhh1f, bih1b, bhh1b);
    lstm_mma_kernel<<<NBLK, 256, LSTM_SMEM>>>(1);

    cls_kernel<<<MM/64, 256>>>(truth, tf, Wc, bc, out);
}

// round 14
// speedup vs baseline: 1.3285x; 1.1229x over previous
#include <cuda_runtime.h>
#include <cuda_bf16.h>
#include <math.h>
#include <stdint.h>

#define BB 32
#define TT 512
#define EE 512
#define HH 512
#define CC 32
#define MM (BB*TT)        /* 16384 token positions, m' = t*32 + b */
#define G4 (4*HH)         /* 2048 gate columns per direction */
#define NBLK 64           /* persistent LSTM grid: 32 blocks per direction */
#define NB2  (NBLK/2)

/* ------------------------ scratch (static device memory) ------------------- */
__device__ __nv_bfloat16 g_embh[(size_t)MM*EE];    /* layer0 GEMM input (bf16) */
__device__ __nv_bfloat16 g_l0h[(size_t)MM*2*HH];   /* layer0 output     (bf16) */
__device__ __nv_bfloat16 g_Wbf[2*(size_t)G4*EE + 2*(size_t)G4*2*HH]; /* Wih bf16 */
__device__ __nv_bfloat16 g_Whbf[4*(size_t)G4*HH];  /* Whh bf16 (4 matrices)    */
__device__ float g_xw0[(size_t)MM*G4];             /* xw forward  [m'][2048]   */
__device__ float g_xw1[(size_t)MM*G4];             /* xw backward [m'][2048]   */
__device__ float g_l1out[(size_t)MM*2*HH];         /* layer1 output [m'][1024] */
__device__ __nv_bfloat16 g_hbuf_bf[2*2*BB*HH];     /* [dir][parity][b][h] bf16 */
__device__ unsigned g_bar_cnt[2] = {0, 0};
__device__ unsigned g_bar_gen[2] = {0, 0};

/* Wbf offsets (Wih) */
#define WOFF_L0F ((size_t)0)
#define WOFF_L0B ((size_t)G4*EE)
#define WOFF_L1F ((size_t)2*G4*EE)
#define WOFF_L1B ((size_t)2*G4*EE + (size_t)G4*2*HH)
/* Whbf offsets (Whh) */
#define WH_L0F ((size_t)0)
#define WH_L0B ((size_t)G4*HH)
#define WH_L1F ((size_t)2*G4*HH)
#define WH_L1B ((size_t)3*G4*HH)

/* ------------------ acq/rel atomic helpers (gpu scope) --------------------- */
__device__ __forceinline__ unsigned ld_acq(const unsigned* p) {
    unsigned v;
    asm volatile("ld.acquire.gpu.global.u32 %0, [%1];" : "=r"(v) : "l"(p) : "memory");
    return v;
}
__device__ __forceinline__ unsigned atom_add_acqrel(unsigned* p, unsigned v) {
    unsigned old;
    asm volatile("atom.acq_rel.gpu.global.add.u32 %0, [%1], %2;"
                 : "=r"(old) : "l"(p), "r"(v) : "memory");
    return old;
}
__device__ __forceinline__ void red_add_rel(unsigned* p, unsigned v) {
    asm volatile("red.release.gpu.global.add.u32 [%0], %1;" :: "l"(p), "r"(v) : "memory");
}
__device__ __forceinline__ void st_rlx(unsigned* p, unsigned v) {
    asm volatile("st.relaxed.gpu.global.u32 [%0], %1;" :: "l"(p), "r"(v) : "memory");
}

/* --------------------- per-direction grid barrier (32 blocks) -------------- */
__device__ __forceinline__ void dir_sync(int dir) {
    __syncthreads();
    if (threadIdx.x == 0) {
        unsigned gen = ld_acq(&g_bar_gen[dir]);
        unsigned prev = atom_add_acqrel(&g_bar_cnt[dir], 1u);
        if (prev == NB2 - 1) {
            st_rlx(&g_bar_cnt[dir], 0u);
            red_add_rel(&g_bar_gen[dir], 1u);
        }
        while (ld_acq(&g_bar_gen[dir]) == gen) { }
    }
    __syncthreads();
}

/* --------------------------- fast activations ------------------------------ */
__device__ __forceinline__ float tanh_fast(float x) {
    float y;
    asm("tanh.approx.f32 %0, %1;" : "=f"(y) : "f"(x));
    return y;
}
__device__ __forceinline__ float sigmoid_fast(float x) {
    return fmaf(tanh_fast(0.5f * x), 0.5f, 0.5f);
}

/* ------------------------------ embedding (f32 -> bf16) -------------------- */
__global__ __launch_bounds__(256) void embed_kernel(const int* __restrict__ x,
                                                    const float* __restrict__ emb) {
    int gid  = blockIdx.x * blockDim.x + threadIdx.x;
    int mp   = gid >> 5;
    int lane = gid & 31;
    int b  = mp & 31;
    int tt = mp >> 5;
    int v  = x[b*TT + tt];
    const float4* src = (const float4*)(emb + (size_t)v*EE);
    __nv_bfloat162* dst = (__nv_bfloat162*)(g_embh + (size_t)mp*EE);
#pragma unroll
    for (int r = 0; r < EE/128; r++) {
        float4 f = src[r*32 + lane];
        dst[(r*32 + lane)*2 + 0] = __floats2bfloat162_rn(f.x, f.y);
        dst[(r*32 + lane)*2 + 1] = __floats2bfloat162_rn(f.z, f.w);
    }
}

/* ------------------ single-launch f32 -> bf16 convert (all 8 W) ------------ */
__global__ __launch_bounds__(256) void conv_all_kernel(
        const float* __restrict__ s0, const float* __restrict__ s1,
        const float* __restrict__ s2, const float* __restrict__ s3,
        const float* __restrict__ s4, const float* __restrict__ s5,
        const float* __restrict__ s6, const float* __restrict__ s7) {
    int z = blockIdx.y;
    const float* src;
    __nv_bfloat16* dst;
    int n4;
    switch (z) {
        case 0: src = s0; dst = g_Wbf  + WOFF_L0F; n4 = G4*EE/4;   break;
        case 1: src = s1; dst = g_Wbf  + WOFF_L0B; n4 = G4*EE/4;   break;
        case 2: src = s2; dst = g_Wbf  + WOFF_L1F; n4 = G4*2*HH/4; break;
        case 3: src = s3; dst = g_Wbf  + WOFF_L1B; n4 = G4*2*HH/4; break;
        case 4: src = s4; dst = g_Whbf + WH_L0F;   n4 = G4*HH/4;   break;
        case 5: src = s5; dst = g_Whbf + WH_L0B;   n4 = G4*HH/4;   break;
        case 6: src = s6; dst = g_Whbf + WH_L1F;   n4 = G4*HH/4;   break;
        default: src = s7; dst = g_Whbf + WH_L1B;  n4 = G4*HH/4;   break;
    }
    int i = blockIdx.x * blockDim.x + threadIdx.x;
    if (i < n4) {
        float4 f = *(const float4*)(src + (size_t)i*4);
        __nv_bfloat162* d = (__nv_bfloat162*)(dst + (size_t)i*4);
        d[0] = __floats2bfloat162_rn(f.x, f.y);
        d[1] = __floats2bfloat162_rn(f.z, f.w);
    }
}

/* ----------------------------- mma helpers --------------------------------- */
__device__ __forceinline__ void ldmatrix_x4(uint32_t& d0, uint32_t& d1,
                                            uint32_t& d2, uint32_t& d3,
                                            uint32_t addr) {
    asm volatile("ldmatrix.sync.aligned.m8n8.x4.shared.b16 {%0,%1,%2,%3}, [%4];"
                 : "=r"(d0), "=r"(d1), "=r"(d2), "=r"(d3) : "r"(addr));
}
__device__ __forceinline__ void mma_bf16(float* c, const uint32_t* a, const uint32_t* b) {
    asm volatile("mma.sync.aligned.m16n8k16.row.col.f32.bf16.bf16.f32 "
                 "{%0,%1,%2,%3}, {%4,%5,%6,%7}, {%8,%9}, {%0,%1,%2,%3};"
                 : "+f"(c[0]), "+f"(c[1]), "+f"(c[2]), "+f"(c[3])
                 : "r"(a[0]), "r"(a[1]), "r"(a[2]), "r"(a[3]), "r"(b[0]), "r"(b[1]));
}

/* ---------------- bf16 tensor-core GEMM: xw = A @ W^T + bih + bhh ---------- */
#define GBM 128
#define GBN 128
#define GBK 32
#define LDS_W 40

__global__ __launch_bounds__(256) void gemm_bf16_kernel(
        int layer,
        const float* __restrict__ bif, const float* __restrict__ bhf,
        const float* __restrict__ bib, const float* __restrict__ bhb) {
    const int K = layer ? 2*HH : EE;
    const __nv_bfloat16* A = layer ? g_l0h : g_embh;
    int dir = blockIdx.z;
    const __nv_bfloat16* W = g_Wbf + (layer ? (dir ? WOFF_L1B : WOFF_L1F)
                                            : (dir ? WOFF_L0B : WOFF_L0F));
    const float* bi = dir ? bib : bif;
    const float* bh = dir ? bhb : bhf;
    float* out = dir ? g_xw1 : g_xw0;

    __shared__ __nv_bfloat16 As[GBM*LDS_W];
    __shared__ __nv_bfloat16 Bs[GBN*LDS_W];

    int t = threadIdx.x;
    int m0 = blockIdx.y * GBM;
    int n0 = blockIdx.x * GBN;
    int warp = t >> 5, lane = t & 31;
    int wm0 = (warp & 3) * 32;
    int wn0 = (warp >> 2) * 64;

    int lr = t >> 2;
    int lc = (t & 3) * 8;
    const __nv_bfloat16* Ag = A + (size_t)(m0 + lr) * K + lc;
    const __nv_bfloat16* Wg = W + (size_t)(n0 + lr) * K + lc;

    float c[2][8][4];
#pragma unroll
    for (int i = 0; i < 2; i++)
#pragma unroll
        for (int j = 0; j < 8; j++)
#pragma unroll
            for (int q = 0; q < 4; q++) c[i][j][q] = 0.f;

    int arow = (lane & 7) + ((lane >> 3) & 1) * 8;
    int acol = (lane >> 4) * 8;
    int brow = ((lane >> 4) * 8) + (lane & 7);
    int bcol = ((lane >> 3) & 1) * 8;

    uint32_t as_base = (uint32_t)__cvta_generic_to_shared(As);
    uint32_t bs_base = (uint32_t)__cvta_generic_to_shared(Bs);

    const int nk = K / GBK;
    uint4 pa0 = *(const uint4*)(Ag);
    uint4 pa1 = *(const uint4*)(Ag + (size_t)64*K);
    uint4 pb0 = *(const uint4*)(Wg);
    uint4 pb1 = *(const uint4*)(Wg + (size_t)64*K);

    for (int kt = 0; kt < nk; kt++) {
        *(uint4*)(As + lr*LDS_W + lc)        = pa0;
        *(uint4*)(As + (lr+64)*LDS_W + lc)   = pa1;
        *(uint4*)(Bs + lr*LDS_W + lc)        = pb0;
        *(uint4*)(Bs + (lr+64)*LDS_W + lc)   = pb1;
        __syncthreads();
        if (kt + 1 < nk) {
            int ko = (kt + 1) * GBK;
            pa0 = *(const uint4*)(Ag + ko);
            pa1 = *(const uint4*)(Ag + (size_t)64*K + ko);
            pb0 = *(const uint4*)(Wg + ko);
            pb1 = *(const uint4*)(Wg + (size_t)64*K + ko);
        }
#pragma unroll
        for (int ks = 0; ks < GBK; ks += 16) {
            uint32_t a[2][4];
            uint32_t b[8][2];
#pragma unroll
            for (int mt = 0; mt < 2; mt++) {
                uint32_t addr = as_base +
                    (uint32_t)(((wm0 + mt*16 + arow)*LDS_W + ks + acol) * 2);
                ldmatrix_x4(a[mt][0], a[mt][1], a[mt][2], a[mt][3], addr);
            }
#pragma unroll
            for (int p = 0; p < 4; p++) {
                uint32_t addr = bs_base +
                    (uint32_t)(((wn0 + p*16 + brow)*LDS_W + ks + bcol) * 2);
                ldmatrix_x4(b[2*p][0], b[2*p][1], b[2*p+1][0], b[2*p+1][1], addr);
            }
#pragma unroll
            for (int mt = 0; mt < 2; mt++)
#pragma unroll
                for (int nt = 0; nt < 8; nt++)
                    mma_bf16(c[mt][nt], a[mt], b[nt]);
        }
        __syncthreads();
    }

    int g  = lane >> 2;
    int cp = (lane & 3) * 2;
#pragma unroll
    for (int nt = 0; nt < 8; nt++) {
        int n = n0 + wn0 + nt*8 + cp;
        float b0 = bi[n]   + bh[n];
        float b1 = bi[n+1] + bh[n+1];
#pragma unroll
        for (int mt = 0; mt < 2; mt++) {
            int r = m0 + wm0 + mt*16 + g;
            float2 v0 = make_float2(c[mt][nt][0] + b0, c[mt][nt][1] + b1);
            float2 v1 = make_float2(c[mt][nt][2] + b0, c[mt][nt][3] + b1);
            *(float2*)(out + (size_t)r*G4 + n)       = v0;
            *(float2*)(out + (size_t)(r+8)*G4 + n)   = v1;
        }
    }
}

/* ------------------- persistent recurrent scan (bf16 MMA) ------------------
 * 32 blocks per direction; each block owns 16 h-columns (64 gate rows).
 * 512 threads / 16 warps: warp tile M16 x N32 x K128 (4-way K-split).       */
#define LW 520                       /* bf16 row stride */
#define GST 66                       /* gate smem row stride (floats) */
#define LSTM_SMEM ((32*LW + 64*LW)*2 + 4*32*GST*4)

__global__ __launch_bounds__(512) void lstm_mma_kernel(int layer) {
    extern __shared__ __align__(16) char smraw[];
    __nv_bfloat16* h_s = (__nv_bfloat16*)smraw;   /* [32][LW] h_{t-1}        */
    __nv_bfloat16* W_s = h_s + 32*LW;             /* [64][LW] Whh slice      */
    float* G_s = (float*)(W_s + 64*LW);           /* [4][32][GST] partials   */

    int t = threadIdx.x;
    int warp = t >> 5, lane = t & 31;
    int dir = blockIdx.x >> 5;
    int hb  = (blockIdx.x & 31) << 4;             /* 16 h-cols per block */
    const __nv_bfloat16* Whh = g_Whbf + (layer ? (dir ? WH_L1B : WH_L1F)
                                               : (dir ? WH_L0B : WH_L0F));
    const float* xw = dir ? g_xw1 : g_xw0;
    __nv_bfloat16* hbuf = g_hbuf_bf + dir*2*BB*HH;

    /* stage Whh slice once: W_s[g*16+j][k] <- Whh[g*512 + hb + j][k]
       64 rows x 512 bf16; 512 threads, 8 threads/row x 64 bf16 */
    {
        int r  = t >> 3;              /* 0..63 */
        int g  = r >> 4, j = r & 15;
        int kq = (t & 7) * 64;
        const uint4* src = (const uint4*)(Whh + (size_t)(g*HH + hb + j)*HH + kq);
        uint4* dst = (uint4*)(W_s + r*LW + kq);
#pragma unroll
        for (int i = 0; i < 8; i++) dst[i] = src[i];
    }

    /* warp tile: mb in {0,16}, nb in {0,32}, kb in {0,128,256,384} */
    int mb = (warp & 1) * 16;
    int nb = ((warp >> 1) & 1) * 32;
    int kb = (warp >> 2) * 128;
    float* Gk = G_s + (warp >> 2) * 32 * GST;

    int arow = (lane & 7) + ((lane >> 3) & 1) * 8;
    int acol = (lane >> 4) * 8;
    int brow = ((lane >> 4) * 8) + (lane & 7);
    int bcol = ((lane >> 3) & 1) * 8;
    uint32_t hs_base = (uint32_t)__cvta_generic_to_shared(h_s);
    uint32_t ws_base = (uint32_t)__cvta_generic_to_shared(W_s);

    /* gate math mapping: 1 thread per (batch gb, h-col gj) cell */
    int gb = t >> 4;                  /* 0..31 */
    int gj = t & 15;                  /* 0..15 */

    float c0 = 0.f;

    for (int it = 0; it < TT; it++) {
        int tstep = dir ? (TT - 1 - it) : it;

        /* prefetch xw for this thread's cell (independent of h) */
        const float* xp = xw + (size_t)(tstep*32 + gb)*G4 + hb + gj;
        float x0 = __ldg(xp + 0*HH);
        float x1 = __ldg(xp + 1*HH);
        float x2 = __ldg(xp + 2*HH);
        float x3 = __ldg(xp + 3*HH);

        /* stage h_{t-1} (32x512 bf16 = 32KB); 16 threads/row x 32 bf16 */
        {
            int r  = t >> 4;
            int kq = (t & 15) * 32;
            uint4* dst = (uint4*)(h_s + r*LW + kq);
            if (it == 0) {
                uint4 z = make_uint4(0u,0u,0u,0u);
#pragma unroll
                for (int i = 0; i < 4; i++) dst[i] = z;
            } else {
                const uint4* src = (const uint4*)(hbuf + ((it & 1) ? BB*HH : 0) + r*HH + kq);
#pragma unroll
                for (int i = 0; i < 4; i++) dst[i] = __ldcg(src + i);
            }
        }
        __syncthreads();

        float acc[4][4];
#pragma unroll
        for (int nt = 0; nt < 4; nt++)
#pragma unroll
            for (int q = 0; q < 4; q++) acc[nt][q] = 0.f;

#pragma unroll
        for (int ks = 0; ks < 8; ks++) {
            uint32_t a[4], b0[2], b1[2], b2[2], b3[2];
            uint32_t addrA = hs_base + (uint32_t)(((mb + arow)*LW + kb + ks*16 + acol) * 2);
            ldmatrix_x4(a[0], a[1], a[2], a[3], addrA);
            uint32_t addrB0 = ws_base + (uint32_t)(((nb + brow)*LW + kb + ks*16 + bcol) * 2);
            ldmatrix_x4(b0[0], b0[1], b1[0], b1[1], addrB0);
            uint32_t addrB1 = ws_base + (uint32_t)(((nb + 16 + brow)*LW + kb + ks*16 + bcol) * 2);
            ldmatrix_x4(b2[0], b2[1], b3[0], b3[1], addrB1);
            mma_bf16(acc[0], a, b0);
            mma_bf16(acc[1], a, b1);
            mma_bf16(acc[2], a, b2);
            mma_bf16(acc[3], a, b3);
        }

        /* C fragments -> gate smem (4-way K-split partials) */
        {
            int g  = lane >> 2;
            int cp = (lane & 3) * 2;
#pragma unroll
            for (int nt = 0; nt < 4; nt++) {
                *(float2*)(Gk + (mb + g)*GST     + nb + nt*8 + cp) = make_float2(acc[nt][0], acc[nt][1]);
                *(float2*)(Gk + (mb + g + 8)*GST + nb + nt*8 + cp) = make_float2(acc[nt][2], acc[nt][3]);
            }
        }
        __syncthreads();

        /* gate math: 1 thread per (gb, gj); torch gate order i, f, g, o */
        {
            float a0 = x0, a1 = x1, a2 = x2, a3 = x3;
#pragma unroll
            for (int s = 0; s < 4; s++) {
                const float* Gp = G_s + s*32*GST + gb*GST;
                a0 += Gp[0*16 + gj];
                a1 += Gp[1*16 + gj];
                a2 += Gp[2*16 + gj];
                a3 += Gp[3*16 + gj];
            }
            float ig = sigmoid_fast(a0);
            float fg = sigmoid_fast(a1);
            float gg = tanh_fast(a2);
            float og = sigmoid_fast(a3);
            c0 = fg*c0 + ig*gg;
            float hv = og * tanh_fast(c0);
            __nv_bfloat16 hbv = __float2bfloat16(hv);

            hbuf[(((it + 1) & 1) ? BB*HH : 0) + gb*HH + hb + gj] = hbv;
            if (layer == 0)
                g_l0h[(size_t)(tstep*32 + gb)*(2*HH) + dir*HH + hb + gj] = hbv;
            else
                g_l1out[(size_t)(tstep*32 + gb)*(2*HH) + dir*HH + hb + gj] = hv;
        }
        dir_sync(dir);
    }
}

/* --------------------- classifier + log_softmax + transpose ---------------- */
__global__ __launch_bounds__(256) void cls_kernel(const float* __restrict__ truth,
        const int* __restrict__ tf, const float* __restrict__ Wc,
        const float* __restrict__ bc, float* __restrict__ out) {
    __shared__ float Fs[64*68];
    __shared__ float Ws[32*68];
    __shared__ float Ls[64*33];
    __shared__ float lse[64];

    int t  = threadIdx.x;
    int p0 = blockIdx.x * 64;
    int p  = t & 63, cg = t >> 6;

    float acc[8];
#pragma unroll
    for (int j = 0; j < 8; j++) acc[j] = 0.f;

    for (int kc = 0; kc < 2*HH; kc += 64) {
        __syncthreads();
#pragma unroll
        for (int pass = 0; pass < 4; pass++) {
            int pp = pass*16 + (t >> 4);
            int kq = (t & 15) * 4;
            *(float4*)(Fs + pp*68 + kq) =
                *(const float4*)(g_l1out + (size_t)(p0 + pp)*(2*HH) + kc + kq);
        }
        {
            int cc = t >> 3, j0 = (t & 7) * 8;
            const float* src = Wc + (size_t)cc*(2*HH + 1) + 1 + kc + j0;
            float* dst = Ws + cc*68 + j0;
#pragma unroll
            for (int i = 0; i < 8; i++) dst[i] = src[i];
        }
        __syncthreads();
#pragma unroll
        for (int kk = 0; kk < 16; kk++) {
            float4 f = *(const float4*)(Fs + p*68 + kk*4);
#pragma unroll
            for (int j = 0; j < 8; j++) {
                float4 wv = *(const float4*)(Ws + (cg*8 + j)*68 + kk*4);
                acc[j] = fmaf(f.x,wv.x, fmaf(f.y,wv.y, fmaf(f.z,wv.z, fmaf(f.w,wv.w, acc[j]))));
            }
        }
    }

    int mp = p0 + p;
    int b  = mp & 31;
    int tt = mp >> 5;
    float past = 0.f;
    if (tt > 0 && tf[0] != 0) past = truth[b*TT + tt - 1];
#pragma unroll
    for (int j = 0; j < 8; j++) {
        int cc = cg*8 + j;
        acc[j] += bc[cc] + past * Wc[(size_t)cc*(2*HH + 1)];
        Ls[p*33 + cc] = acc[j];
    }
    __syncthreads();
    if (t < 64) {
        float m = -1e30f;
#pragma unroll
        for (int cc = 0; cc < CC; cc++) m = fmaxf(m, Ls[t*33 + cc]);
        float s = 0.f;
#pragma unroll
        for (int cc = 0; cc < CC; cc++) s += expf(Ls[t*33 + cc] - m);
        lse[t] = m + logf(s);
    }
    __syncthreads();
    {
        float l = lse[p];
#pragma unroll
        for (int j = 0; j < 8; j++) {
            int cc = cg*8 + j;
            out[(size_t)b*CC*TT + (size_t)cc*TT + tt] = Ls[p*33 + cc] - l;
        }
    }
}

/* ------------------------------- launch ------------------------------------ */
extern "C" void kernel_launch(void* const* d_in, const int* in_sizes, int n_in,
                              void* d_out, int out_size) {
    (void)in_sizes; (void)n_in; (void)out_size;
    const int*   x     = (const int*)  d_in[0];
    const float* truth = (const float*)d_in[1];
    const int*   tf    = (const int*)  d_in[2];
    const float* emb   = (const float*)d_in[3];
    const float* Wih0f = (const float*)d_in[4];
    const float* Whh0f = (const float*)d_in[5];
    const float* bih0f = (const float*)d_in[6];
    const float* bhh0f = (const float*)d_in[7];
    const float* Wih0b = (const float*)d_in[8];
    const float* Whh0b = (const float*)d_in[9];
    const float* bih0b = (const float*)d_in[10];
    const float* bhh0b = (const float*)d_in[11];
    const float* Wih1f = (const float*)d_in[12];
    const float* Whh1f = (const float*)d_in[13];
    const float* bih1f = (const float*)d_in[14];
    const float* bhh1f = (const float*)d_in[15];
    const float* Wih1b = (const float*)d_in[16];
    const float* Whh1b = (const float*)d_in[17];
    const float* bih1b = (const float*)d_in[18];
    const float* bhh1b = (const float*)d_in[19];
    const float* Wc    = (const float*)d_in[20];
    const float* bc    = (const float*)d_in[21];
    float* out = (float*)d_out;

    cudaFuncSetAttribute(lstm_mma_kernel,
                         cudaFuncAttributeMaxDynamicSharedMemorySize, LSTM_SMEM);

    /* launch order fixes ncu -s 5 -c 1 onto lstm1 (launch #6):
       conv(1) embed(2) gemm0(3) lstm0(4) gemm1(5) lstm1(6) cls(7) */
    dim3 gc(2048, 8);
    conv_all_kernel<<<gc, 256>>>(Wih0f, Wih0b, Wih1f, Wih1b,
                                 Whh0f, Whh0b, Whh1f, Whh1b);

    embed_kernel<<<MM/8, 256>>>(x, emb);

    dim3 g0(G4/GBN, MM/GBM, 2);   /* 16 x 128 x 2 */
    gemm_bf16_kernel<<<g0, 256>>>(0, bih0f, bhh0f, bih0b, bhh0b);
    lstm_mma_kernel<<<NBLK, 512, LSTM_SMEM>>>(0);

    gemm_bf16_kernel<<<g0, 256>>>(1, bih1f, bhh1f, bih1b, bhh1b);
    lstm_mma_kernel<<<NBLK, 512, LSTM_SMEM>>>(1);

    cls_kernel<<<MM/64, 256>>>(truth, tf, Wc, bc, out);
}

// round 15
// speedup vs baseline: 1.3335x; 1.0038x over previous
#include <cuda_runtime.h>
#include <cuda_bf16.h>
#include <math.h>
#include <stdint.h>

#define BB 32
#define TT 512
#define EE 512
#define HH 512
#define CC 32
#define MM (BB*TT)        /* 16384 token positions, m' = t*32 + b */
#define G4 (4*HH)         /* 2048 gate columns per direction */
#define NBLK 64           /* persistent LSTM grid: 32 blocks per direction */
#define NB2  (NBLK/2)

/* ------------------------ scratch (static device memory) ------------------- */
__device__ __nv_bfloat16 g_embh[(size_t)MM*EE];    /* layer0 GEMM input (bf16) */
__device__ __nv_bfloat16 g_l0h[(size_t)MM*2*HH];   /* layer0 output     (bf16) */
__device__ __nv_bfloat16 g_Wbf[2*(size_t)G4*EE + 2*(size_t)G4*2*HH]; /* Wih bf16 */
__device__ __nv_bfloat16 g_Whbf[4*(size_t)G4*HH];  /* Whh bf16 (4 matrices)    */
__device__ float g_xw0[(size_t)MM*G4];             /* xw forward  [m'][2048]   */
__device__ float g_xw1[(size_t)MM*G4];             /* xw backward [m'][2048]   */
__device__ float g_l1out[(size_t)MM*2*HH];         /* layer1 output [m'][1024] */
__device__ __nv_bfloat16 g_hbuf_bf[2*2*BB*HH];     /* [dir][parity][b][h] bf16 */
__device__ unsigned g_bar_cnt[2] = {0, 0};
__device__ unsigned g_bar_gen[2] = {0, 0};

/* Wbf offsets (Wih) */
#define WOFF_L0F ((size_t)0)
#define WOFF_L0B ((size_t)G4*EE)
#define WOFF_L1F ((size_t)2*G4*EE)
#define WOFF_L1B ((size_t)2*G4*EE + (size_t)G4*2*HH)
/* Whbf offsets (Whh) */
#define WH_L0F ((size_t)0)
#define WH_L0B ((size_t)G4*HH)
#define WH_L1F ((size_t)2*G4*HH)
#define WH_L1B ((size_t)3*G4*HH)

/* ------------------ acq/rel atomic helpers (gpu scope) --------------------- */
__device__ __forceinline__ unsigned ld_acq(const unsigned* p) {
    unsigned v;
    asm volatile("ld.acquire.gpu.global.u32 %0, [%1];" : "=r"(v) : "l"(p) : "memory");
    return v;
}
__device__ __forceinline__ unsigned atom_add_acqrel(unsigned* p, unsigned v) {
    unsigned old;
    asm volatile("atom.acq_rel.gpu.global.add.u32 %0, [%1], %2;"
                 : "=r"(old) : "l"(p), "r"(v) : "memory");
    return old;
}
__device__ __forceinline__ void red_add_rel(unsigned* p, unsigned v) {
    asm volatile("red.release.gpu.global.add.u32 [%0], %1;" :: "l"(p), "r"(v) : "memory");
}
__device__ __forceinline__ void st_rlx(unsigned* p, unsigned v) {
    asm volatile("st.relaxed.gpu.global.u32 [%0], %1;" :: "l"(p), "r"(v) : "memory");
}

/* --------------------- per-direction grid barrier (32 blocks) -------------- */
__device__ __forceinline__ void dir_sync(int dir) {
    __syncthreads();
    if (threadIdx.x == 0) {
        unsigned gen = ld_acq(&g_bar_gen[dir]);
        unsigned prev = atom_add_acqrel(&g_bar_cnt[dir], 1u);
        if (prev == NB2 - 1) {
            st_rlx(&g_bar_cnt[dir], 0u);
            red_add_rel(&g_bar_gen[dir], 1u);
        }
        while (ld_acq(&g_bar_gen[dir]) == gen) { }
    }
    __syncthreads();
}

/* --------------------------- fast activations ------------------------------ */
__device__ __forceinline__ float tanh_fast(float x) {
    float y;
    asm("tanh.approx.f32 %0, %1;" : "=f"(y) : "f"(x));
    return y;
}
__device__ __forceinline__ float sigmoid_fast(float x) {
    return fmaf(tanh_fast(0.5f * x), 0.5f, 0.5f);
}

/* ------------------------------ embedding (f32 -> bf16) -------------------- */
__global__ __launch_bounds__(256) void embed_kernel(const int* __restrict__ x,
                                                    const float* __restrict__ emb) {
    int gid  = blockIdx.x * blockDim.x + threadIdx.x;
    int mp   = gid >> 5;
    int lane = gid & 31;
    int b  = mp & 31;
    int tt = mp >> 5;
    int v  = x[b*TT + tt];
    const float4* src = (const float4*)(emb + (size_t)v*EE);
    __nv_bfloat162* dst = (__nv_bfloat162*)(g_embh + (size_t)mp*EE);
#pragma unroll
    for (int r = 0; r < EE/128; r++) {
        float4 f = src[r*32 + lane];
        dst[(r*32 + lane)*2 + 0] = __floats2bfloat162_rn(f.x, f.y);
        dst[(r*32 + lane)*2 + 1] = __floats2bfloat162_rn(f.z, f.w);
    }
}

/* ------------------ single-launch f32 -> bf16 convert (all 8 W) ------------ */
__global__ __launch_bounds__(256) void conv_all_kernel(
        const float* __restrict__ s0, const float* __restrict__ s1,
        const float* __restrict__ s2, const float* __restrict__ s3,
        const float* __restrict__ s4, const float* __restrict__ s5,
        const float* __restrict__ s6, const float* __restrict__ s7) {
    int z = blockIdx.y;
    const float* src;
    __nv_bfloat16* dst;
    int n4;
    switch (z) {
        case 0: src = s0; dst = g_Wbf  + WOFF_L0F; n4 = G4*EE/4;   break;
        case 1: src = s1; dst = g_Wbf  + WOFF_L0B; n4 = G4*EE/4;   break;
        case 2: src = s2; dst = g_Wbf  + WOFF_L1F; n4 = G4*2*HH/4; break;
        case 3: src = s3; dst = g_Wbf  + WOFF_L1B; n4 = G4*2*HH/4; break;
        case 4: src = s4; dst = g_Whbf + WH_L0F;   n4 = G4*HH/4;   break;
        case 5: src = s5; dst = g_Whbf + WH_L0B;   n4 = G4*HH/4;   break;
        case 6: src = s6; dst = g_Whbf + WH_L1F;   n4 = G4*HH/4;   break;
        default: src = s7; dst = g_Whbf + WH_L1B;  n4 = G4*HH/4;   break;
    }
    int i = blockIdx.x * blockDim.x + threadIdx.x;
    if (i < n4) {
        float4 f = *(const float4*)(src + (size_t)i*4);
        __nv_bfloat162* d = (__nv_bfloat162*)(dst + (size_t)i*4);
        d[0] = __floats2bfloat162_rn(f.x, f.y);
        d[1] = __floats2bfloat162_rn(f.z, f.w);
    }
}

/* ----------------------------- mma helpers --------------------------------- */
__device__ __forceinline__ void ldmatrix_x4(uint32_t& d0, uint32_t& d1,
                                            uint32_t& d2, uint32_t& d3,
                                            uint32_t addr) {
    asm volatile("ldmatrix.sync.aligned.m8n8.x4.shared.b16 {%0,%1,%2,%3}, [%4];"
                 : "=r"(d0), "=r"(d1), "=r"(d2), "=r"(d3) : "r"(addr));
}
__device__ __forceinline__ void mma_bf16(float* c, const uint32_t* a, const uint32_t* b) {
    asm volatile("mma.sync.aligned.m16n8k16.row.col.f32.bf16.bf16.f32 "
                 "{%0,%1,%2,%3}, {%4,%5,%6,%7}, {%8,%9}, {%0,%1,%2,%3};"
                 : "+f"(c[0]), "+f"(c[1]), "+f"(c[2]), "+f"(c[3])
                 : "r"(a[0]), "r"(a[1]), "r"(a[2]), "r"(a[3]), "r"(b[0]), "r"(b[1]));
}

/* ---------------- bf16 tensor-core GEMM: xw = A @ W^T + bih + bhh ---------- */
#define GBM 128
#define GBN 128
#define GBK 32
#define LDS_W 40

__global__ __launch_bounds__(256) void gemm_bf16_kernel(
        int layer,
        const float* __restrict__ bif, const float* __restrict__ bhf,
        const float* __restrict__ bib, const float* __restrict__ bhb) {
    const int K = layer ? 2*HH : EE;
    const __nv_bfloat16* A = layer ? g_l0h : g_embh;
    int dir = blockIdx.z;
    const __nv_bfloat16* W = g_Wbf + (layer ? (dir ? WOFF_L1B : WOFF_L1F)
                                            : (dir ? WOFF_L0B : WOFF_L0F));
    const float* bi = dir ? bib : bif;
    const float* bh = dir ? bhb : bhf;
    float* out = dir ? g_xw1 : g_xw0;

    __shared__ __nv_bfloat16 As[GBM*LDS_W];
    __shared__ __nv_bfloat16 Bs[GBN*LDS_W];

    int t = threadIdx.x;
    int m0 = blockIdx.y * GBM;
    int n0 = blockIdx.x * GBN;
    int warp = t >> 5, lane = t & 31;
    int wm0 = (warp & 3) * 32;
    int wn0 = (warp >> 2) * 64;

    int lr = t >> 2;
    int lc = (t & 3) * 8;
    const __nv_bfloat16* Ag = A + (size_t)(m0 + lr) * K + lc;
    const __nv_bfloat16* Wg = W + (size_t)(n0 + lr) * K + lc;

    float c[2][8][4];
#pragma unroll
    for (int i = 0; i < 2; i++)
#pragma unroll
        for (int j = 0; j < 8; j++)
#pragma unroll
            for (int q = 0; q < 4; q++) c[i][j][q] = 0.f;

    int arow = (lane & 7) + ((lane >> 3) & 1) * 8;
    int acol = (lane >> 4) * 8;
    int brow = ((lane >> 4) * 8) + (lane & 7);
    int bcol = ((lane >> 3) & 1) * 8;

    uint32_t as_base = (uint32_t)__cvta_generic_to_shared(As);
    uint32_t bs_base = (uint32_t)__cvta_generic_to_shared(Bs);

    const int nk = K / GBK;
    uint4 pa0 = *(const uint4*)(Ag);
    uint4 pa1 = *(const uint4*)(Ag + (size_t)64*K);
    uint4 pb0 = *(const uint4*)(Wg);
    uint4 pb1 = *(const uint4*)(Wg + (size_t)64*K);

    for (int kt = 0; kt < nk; kt++) {
        *(uint4*)(As + lr*LDS_W + lc)        = pa0;
        *(uint4*)(As + (lr+64)*LDS_W + lc)   = pa1;
        *(uint4*)(Bs + lr*LDS_W + lc)        = pb0;
        *(uint4*)(Bs + (lr+64)*LDS_W + lc)   = pb1;
        __syncthreads();
        if (kt + 1 < nk) {
            int ko = (kt + 1) * GBK;
            pa0 = *(const uint4*)(Ag + ko);
            pa1 = *(const uint4*)(Ag + (size_t)64*K + ko);
            pb0 = *(const uint4*)(Wg + ko);
            pb1 = *(const uint4*)(Wg + (size_t)64*K + ko);
        }
#pragma unroll
        for (int ks = 0; ks < GBK; ks += 16) {
            uint32_t a[2][4];
            uint32_t b[8][2];
#pragma unroll
            for (int mt = 0; mt < 2; mt++) {
                uint32_t addr = as_base +
                    (uint32_t)(((wm0 + mt*16 + arow)*LDS_W + ks + acol) * 2);
                ldmatrix_x4(a[mt][0], a[mt][1], a[mt][2], a[mt][3], addr);
            }
#pragma unroll
            for (int p = 0; p < 4; p++) {
                uint32_t addr = bs_base +
                    (uint32_t)(((wn0 + p*16 + brow)*LDS_W + ks + bcol) * 2);
                ldmatrix_x4(b[2*p][0], b[2*p][1], b[2*p+1][0], b[2*p+1][1], addr);
            }
#pragma unroll
            for (int mt = 0; mt < 2; mt++)
#pragma unroll
                for (int nt = 0; nt < 8; nt++)
                    mma_bf16(c[mt][nt], a[mt], b[nt]);
        }
        __syncthreads();
    }

    int g  = lane >> 2;
    int cp = (lane & 3) * 2;
#pragma unroll
    for (int nt = 0; nt < 8; nt++) {
        int n = n0 + wn0 + nt*8 + cp;
        float b0 = bi[n]   + bh[n];
        float b1 = bi[n+1] + bh[n+1];
#pragma unroll
        for (int mt = 0; mt < 2; mt++) {
            int r = m0 + wm0 + mt*16 + g;
            float2 v0 = make_float2(c[mt][nt][0] + b0, c[mt][nt][1] + b1);
            float2 v1 = make_float2(c[mt][nt][2] + b0, c[mt][nt][3] + b1);
            *(float2*)(out + (size_t)r*G4 + n)       = v0;
            *(float2*)(out + (size_t)(r+8)*G4 + n)   = v1;
        }
    }
}

/* ------------------- persistent recurrent scan (bf16 MMA) ------------------
 * 32 blocks per direction; each block owns 16 h-columns (64 gate rows).
 * 512 threads / 16 warps: warp tile M16 x N32 x K128 (4-way K-split).       */
#define LW 520                       /* bf16 row stride */
#define GST 66                       /* gate smem row stride (floats) */
#define LSTM_SMEM ((32*LW + 64*LW)*2 + 4*32*GST*4)

__global__ __launch_bounds__(512) void lstm_mma_kernel(int layer) {
    extern __shared__ __align__(16) char smraw[];
    __nv_bfloat16* h_s = (__nv_bfloat16*)smraw;   /* [32][LW] h_{t-1}        */
    __nv_bfloat16* W_s = h_s + 32*LW;             /* [64][LW] Whh slice      */
    float* G_s = (float*)(W_s + 64*LW);           /* [4][32][GST] partials   */

    int t = threadIdx.x;
    int warp = t >> 5, lane = t & 31;
    int dir = blockIdx.x >> 5;
    int hb  = (blockIdx.x & 31) << 4;             /* 16 h-cols per block */
    const __nv_bfloat16* Whh = g_Whbf + (layer ? (dir ? WH_L1B : WH_L1F)
                                               : (dir ? WH_L0B : WH_L0F));
    const float* xw = dir ? g_xw1 : g_xw0;
    __nv_bfloat16* hbuf = g_hbuf_bf + dir*2*BB*HH;

    /* stage Whh slice once: W_s[g*16+j][k] <- Whh[g*512 + hb + j][k]
       64 rows x 512 bf16; 512 threads, 8 threads/row x 64 bf16 */
    {
        int r  = t >> 3;              /* 0..63 */
        int g  = r >> 4, j = r & 15;
        int kq = (t & 7) * 64;
        const uint4* src = (const uint4*)(Whh + (size_t)(g*HH + hb + j)*HH + kq);
        uint4* dst = (uint4*)(W_s + r*LW + kq);
#pragma unroll
        for (int i = 0; i < 8; i++) dst[i] = src[i];
    }

    /* warp tile: mb in {0,16}, nb in {0,32}, kb in {0,128,256,384} */
    int mb = (warp & 1) * 16;
    int nb = ((warp >> 1) & 1) * 32;
    int kb = (warp >> 2) * 128;
    float* Gk = G_s + (warp >> 2) * 32 * GST;

    int arow = (lane & 7) + ((lane >> 3) & 1) * 8;
    int acol = (lane >> 4) * 8;
    int brow = ((lane >> 4) * 8) + (lane & 7);
    int bcol = ((lane >> 3) & 1) * 8;
    uint32_t hs_base = (uint32_t)__cvta_generic_to_shared(h_s);
    uint32_t ws_base = (uint32_t)__cvta_generic_to_shared(W_s);

    /* gate math mapping: 1 thread per (batch gb, h-col gj) cell */
    int gb = t >> 4;                  /* 0..31 */
    int gj = t & 15;                  /* 0..15 */

    float c0 = 0.f;

    for (int it = 0; it < TT; it++) {
        int tstep = dir ? (TT - 1 - it) : it;

        /* prefetch xw for this thread's cell (independent of h) */
        const float* xp = xw + (size_t)(tstep*32 + gb)*G4 + hb + gj;
        float x0 = __ldg(xp + 0*HH);
        float x1 = __ldg(xp + 1*HH);
        float x2 = __ldg(xp + 2*HH);
        float x3 = __ldg(xp + 3*HH);

        /* stage h_{t-1} (32x512 bf16 = 32KB); 16 threads/row x 32 bf16 */
        {
            int r  = t >> 4;
            int kq = (t & 15) * 32;
            uint4* dst = (uint4*)(h_s + r*LW + kq);
            if (it == 0) {
                uint4 z = make_uint4(0u,0u,0u,0u);
#pragma unroll
                for (int i = 0; i < 4; i++) dst[i] = z;
            } else {
                const uint4* src = (const uint4*)(hbuf + ((it & 1) ? BB*HH : 0) + r*HH + kq);
#pragma unroll
                for (int i = 0; i < 4; i++) dst[i] = __ldcg(src + i);
            }
        }
        __syncthreads();

        float acc[4][4];
#pragma unroll
        for (int nt = 0; nt < 4; nt++)
#pragma unroll
            for (int q = 0; q < 4; q++) acc[nt][q] = 0.f;

#pragma unroll
        for (int ks = 0; ks < 8; ks++) {
            uint32_t a[4], b0[2], b1[2], b2[2], b3[2];
            uint32_t addrA = hs_base + (uint32_t)(((mb + arow)*LW + kb + ks*16 + acol) * 2);
            ldmatrix_x4(a[0], a[1], a[2], a[3], addrA);
            uint32_t addrB0 = ws_base + (uint32_t)(((nb + brow)*LW + kb + ks*16 + bcol) * 2);
            ldmatrix_x4(b0[0], b0[1], b1[0], b1[1], addrB0);
            uint32_t addrB1 = ws_base + (uint32_t)(((nb + 16 + brow)*LW + kb + ks*16 + bcol) * 2);
            ldmatrix_x4(b2[0], b2[1], b3[0], b3[1], addrB1);
            mma_bf16(acc[0], a, b0);
            mma_bf16(acc[1], a, b1);
            mma_bf16(acc[2], a, b2);
            mma_bf16(acc[3], a, b3);
        }

        /* C fragments -> gate smem (4-way K-split partials) */
        {
            int g  = lane >> 2;
            int cp = (lane & 3) * 2;
#pragma unroll
            for (int nt = 0; nt < 4; nt++) {
                *(float2*)(Gk + (mb + g)*GST     + nb + nt*8 + cp) = make_float2(acc[nt][0], acc[nt][1]);
                *(float2*)(Gk + (mb + g + 8)*GST + nb + nt*8 + cp) = make_float2(acc[nt][2], acc[nt][3]);
            }
        }
        __syncthreads();

        /* gate math: 1 thread per (gb, gj); torch gate order i, f, g, o */
        {
            float a0 = x0, a1 = x1, a2 = x2, a3 = x3;
#pragma unroll
            for (int s = 0; s < 4; s++) {
                const float* Gp = G_s + s*32*GST + gb*GST;
                a0 += Gp[0*16 + gj];
                a1 += Gp[1*16 + gj];
                a2 += Gp[2*16 + gj];
                a3 += Gp[3*16 + gj];
            }
            float ig = sigmoid_fast(a0);
            float fg = sigmoid_fast(a1);
            float gg = tanh_fast(a2);
            float og = sigmoid_fast(a3);
            c0 = fg*c0 + ig*gg;
            float hv = og * tanh_fast(c0);
            __nv_bfloat16 hbv = __float2bfloat16(hv);

            hbuf[(((it + 1) & 1) ? BB*HH : 0) + gb*HH + hb + gj] = hbv;
            if (layer == 0)
                g_l0h[(size_t)(tstep*32 + gb)*(2*HH) + dir*HH + hb + gj] = hbv;
            else
                g_l1out[(size_t)(tstep*32 + gb)*(2*HH) + dir*HH + hb + gj] = hv;
        }
        dir_sync(dir);
    }
}

/* --------------------- classifier + log_softmax + transpose ---------------- */
__global__ __launch_bounds__(256) void cls_kernel(const float* __restrict__ truth,
        const int* __restrict__ tf, const float* __restrict__ Wc,
        const float* __restrict__ bc, float* __restrict__ out) {
    __shared__ float Fs[64*68];
    __shared__ float Ws[32*68];
    __shared__ float Ls[64*33];
    __shared__ float lse[64];

    int t  = threadIdx.x;
    int p0 = blockIdx.x * 64;
    int p  = t & 63, cg = t >> 6;

    float acc[8];
#pragma unroll
    for (int j = 0; j < 8; j++) acc[j] = 0.f;

    for (int kc = 0; kc < 2*HH; kc += 64) {
        __syncthreads();
#pragma unroll
        for (int pass = 0; pass < 4; pass++) {
            int pp = pass*16 + (t >> 4);
            int kq = (t & 15) * 4;
            *(float4*)(Fs + pp*68 + kq) =
                *(const float4*)(g_l1out + (size_t)(p0 + pp)*(2*HH) + kc + kq);
        }
        {
            int cc = t >> 3, j0 = (t & 7) * 8;
            const float* src = Wc + (size_t)cc*(2*HH + 1) + 1 + kc + j0;
            float* dst = Ws + cc*68 + j0;
#pragma unroll
            for (int i = 0; i < 8; i++) dst[i] = src[i];
        }
        __syncthreads();
#pragma unroll
        for (int kk = 0; kk < 16; kk++) {
            float4 f = *(const float4*)(Fs + p*68 + kk*4);
#pragma unroll
            for (int j = 0; j < 8; j++) {
                float4 wv = *(const float4*)(Ws + (cg*8 + j)*68 + kk*4);
                acc[j] = fmaf(f.x,wv.x, fmaf(f.y,wv.y, fmaf(f.z,wv.z, fmaf(f.w,wv.w, acc[j]))));
            }
        }
    }

    int mp = p0 + p;
    int b  = mp & 31;
    int tt = mp >> 5;
    float past = 0.f;
    if (tt > 0 && tf[0] != 0) past = truth[b*TT + tt - 1];
#pragma unroll
    for (int j = 0; j < 8; j++) {
        int cc = cg*8 + j;
        acc[j] += bc[cc] + past * Wc[(size_t)cc*(2*HH + 1)];
        Ls[p*33 + cc] = acc[j];
    }
    __syncthreads();
    if (t < 64) {
        float m = -1e30f;
#pragma unroll
        for (int cc = 0; cc < CC; cc++) m = fmaxf(m, Ls[t*33 + cc]);
        float s = 0.f;
#pragma unroll
        for (int cc = 0; cc < CC; cc++) s += expf(Ls[t*33 + cc] - m);
        lse[t] = m + logf(s);
    }
    __syncthreads();
    {
        float l = lse[p];
#pragma unroll
        for (int j = 0; j < 8; j++) {
            int cc = cg*8 + j;
            out[(size_t)b*CC*TT + (size_t)cc*TT + tt] = Ls[p*33 + cc] - l;
        }
    }
}

/* ------------------------------- launch ------------------------------------ */
extern "C" void kernel_launch(void* const* d_in, const int* in_sizes, int n_in,
                              void* d_out, int out_size) {
    (void)in_sizes; (void)n_in; (void)out_size;
    const int*   x     = (const int*)  d_in[0];
    const float* truth = (const float*)d_in[1];
    const int*   tf    = (const int*)  d_in[2];
    const float* emb   = (const float*)d_in[3];
    const float* Wih0f = (const float*)d_in[4];
    const float* Whh0f = (const float*)d_in[5];
    const float* bih0f = (const float*)d_in[6];
    const float* bhh0f = (const float*)d_in[7];
    const float* Wih0b = (const float*)d_in[8];
    const float* Whh0b = (const float*)d_in[9];
    const float* bih0b = (const float*)d_in[10];
    const float* bhh0b = (const float*)d_in[11];
    const float* Wih1f = (const float*)d_in[12];
    const float* Whh1f = (const float*)d_in[13];
    const float* bih1f = (const float*)d_in[14];
    const float* bhh1f = (const float*)d_in[15];
    const float* Wih1b = (const float*)d_in[16];
    const float* Whh1b = (const float*)d_in[17];
    const float* bih1b = (const float*)d_in[18];
    const float* bhh1b = (const float*)d_in[19];
    const float* Wc    = (const float*)d_in[20];
    const float* bc    = (const float*)d_in[21];
    float* out = (float*)d_out;

    cudaFuncSetAttribute(lstm_mma_kernel,
                         cudaFuncAttributeMaxDynamicSharedMemorySize, LSTM_SMEM);

    /* launch order fixes ncu -s 5 -c 1 onto lstm1 (launch #6):
       conv(1) embed(2) gemm0(3) lstm0(4) gemm1(5) lstm1(6) cls(7) */
    dim3 gc(2048, 8);
    conv_all_kernel<<<gc, 256>>>(Wih0f, Wih0b, Wih1f, Wih1b,
                                 Whh0f, Whh0b, Whh1f, Whh1b);

    embed_kernel<<<MM/8, 256>>>(x, emb);

    dim3 g0(G4/GBN, MM/GBM, 2);   /* 16 x 128 x 2 */
    gemm_bf16_kernel<<<g0, 256>>>(0, bih0f, bhh0f, bih0b, bhh0b);
    lstm_mma_kernel<<<NBLK, 512, LSTM_SMEM>>>(0);

    gemm_bf16_kernel<<<g0, 256>>>(1, bih1f, bhh1f, bih1b, bhh1b);
    lstm_mma_kernel<<<NBLK, 512, LSTM_SMEM>>>(1);

    cls_kernel<<<MM/64, 256>>>(truth, tf, Wc, bc, out);
}